// round 10
// baseline (speedup 1.0000x reference)
#include <cuda_runtime.h>
#include <math.h>
#include <float.h>

// ---------------- problem constants ----------------
#define G_      32
#define EPG     16384                 // edges per graph
#define EDGES   (G_ * EPG)
#define H_      128
#define NT_MAX  32768

static const int NCUR_H[4] = {1024, 820, 656, 525};
static const int KSEL_H[4] = {820, 656, 525, 420};

// gemm smem: meanS 64x132 + W 2x16x128 + H 2x16x64  (floats)
#define SMEM_GEMM_BYTES ((64 * 132 + 2 * 16 * 128 + 2 * 16 * 64) * 4)
// mega smem: 5 x 4KB arrays + 32KB reduce/scratch region
#define MEGA_SMEM (5 * 4096 + 32 * 128 * 2 * 4)

// ---------------- device scratch (double-buffered CSR) ----------------
__device__ __align__(16) float g_bufA[NT_MAX * H_];  // pooled h (input of next block)
__device__ __align__(16) float g_bufB[NT_MAX * H_];  // conv out -> BN'd h
__device__ int   g_cnt0[NT_MAX],  g_cnt1[NT_MAX];
__device__ int   g_off0[NT_MAX],  g_off1[NT_MAX];    // absolute csr base per node
__device__ int   g_csr0[EDGES],   g_csr1[EDGES];     // neighbor global row ids grouped by dst
__device__ float g_score[NT_MAX];
__device__ __align__(16) float g_colsum[4 * H_];
__device__ __align__(16) float g_colsq [4 * H_];
__device__ float g_flat[G_ * 1024];

// ---------------- csr0: per-graph count+scan+fill for input edges (writes buffer 0) ----------------
__global__ __launch_bounds__(1024)
void csr0_kernel(const int* __restrict__ ei) {
    __shared__ int cnt[1024], off[1024], cur[1024];
    __shared__ int wsum[32];
    int g = blockIdx.x, tid = threadIdx.x;
    int lane = tid & 31, wid = tid >> 5;
    cnt[tid] = 0;
    __syncthreads();
    const int* srcp = ei + g * EPG;
    const int* dstp = ei + EDGES + g * EPG;
    for (int e = tid; e < EPG; e += 1024)
        atomicAdd(&cnt[dstp[e] - (g << 10)], 1);
    __syncthreads();
    int v = cnt[tid];
    int inc = v;
    #pragma unroll
    for (int o = 1; o < 32; o <<= 1) {
        int t = __shfl_up_sync(0xffffffffu, inc, o);
        if (lane >= o) inc += t;
    }
    if (lane == 31) wsum[wid] = inc;
    __syncthreads();
    if (wid == 0) {
        int ws = wsum[lane], wi = ws;
        #pragma unroll
        for (int o = 1; o < 32; o <<= 1) {
            int t = __shfl_up_sync(0xffffffffu, wi, o);
            if (lane >= o) wi += t;
        }
        wsum[lane] = wi - ws;
    }
    __syncthreads();
    int ex = wsum[wid] + inc - v;
    off[tid] = ex;
    g_off0[g * 1024 + tid] = g * EPG + ex;
    g_cnt0[g * 1024 + tid] = v;
    cur[tid] = 0;
    __syncthreads();
    for (int e = tid; e < EPG; e += 1024) {
        int s = srcp[e];
        int d = dstp[e] - (g << 10);
        int pos = atomicAdd(&cur[d], 1);
        g_csr0[g * EPG + off[d] + pos] = s;
    }
    if (g == 0 && tid < 4 * H_) { g_colsum[tid] = 0.f; g_colsq[tid] = 0.f; }
}

// ---------------- fused gather-mean + GEMM + BN-stats (64-row tile) ----------------
__global__ __launch_bounds__(256, 3)
void gemm_kernel(const float* __restrict__ x, int first, int slot, int csrsel,
                 const float* __restrict__ Wl, const float* __restrict__ Wr,
                 const float* __restrict__ bb, int nt) {
    extern __shared__ float smem[];
    float* meanS = smem;                        // [64][132]
    float* WshB  = smem + 64 * 132;             // [2][16][128]
    float* HshB  = WshB + 2 * 16 * 128;         // [2][16][64]
    #define WSH(b,k,c) WshB[(b) * 2048 + (k) * 128 + (c)]
    #define HSH(b,k,m) HshB[(b) * 1024 + (k) * 64 + (m)]

    const int* cnti = csrsel ? g_cnt1 : g_cnt0;
    const int* offi = csrsel ? g_off1 : g_off0;
    const int* csri = csrsel ? g_csr1 : g_csr0;

    const float* hin = first ? x : g_bufA;
    int row0 = blockIdx.x * 64;
    int tid = threadIdx.x;
    int w = tid >> 5, lane = tid & 31;
    int tx = tid & 15, ty = tid >> 4;
    int rm = ty * 4, cn = tx * 4;

    // prefetch W block 0 behind the gather
    float4 pw[2];
    #pragma unroll
    for (int i = 0; i < 2; i++) {
        int idx = tid * 2 + i;
        int kk = idx >> 5, c = (idx & 31) * 4;
        pw[i] = *(const float4*)(Wl + (size_t)kk * H_ + c);
    }

    // ---- phase 1: gather means (8 rows per warp, 8 loads in flight) ----
    for (int i = 0; i < 8; i++) {
        int rl = w * 8 + i;
        int row = row0 + rl;
        float4 acc = make_float4(0.f, 0.f, 0.f, 0.f);
        if (row < nt) {
            int deg  = cnti[row];
            int base = offi[row];
            int j = 0;
            for (; j + 8 <= deg; j += 8) {
                int s0 = csri[base + j + 0];
                int s1 = csri[base + j + 1];
                int s2 = csri[base + j + 2];
                int s3 = csri[base + j + 3];
                int s4 = csri[base + j + 4];
                int s5 = csri[base + j + 5];
                int s6 = csri[base + j + 6];
                int s7 = csri[base + j + 7];
                float4 v0 = *((const float4*)(hin + (size_t)s0 * H_) + lane);
                float4 v1 = *((const float4*)(hin + (size_t)s1 * H_) + lane);
                float4 v2 = *((const float4*)(hin + (size_t)s2 * H_) + lane);
                float4 v3 = *((const float4*)(hin + (size_t)s3 * H_) + lane);
                float4 v4 = *((const float4*)(hin + (size_t)s4 * H_) + lane);
                float4 v5 = *((const float4*)(hin + (size_t)s5 * H_) + lane);
                float4 v6 = *((const float4*)(hin + (size_t)s6 * H_) + lane);
                float4 v7 = *((const float4*)(hin + (size_t)s7 * H_) + lane);
                acc.x += ((v0.x + v1.x) + (v2.x + v3.x)) + ((v4.x + v5.x) + (v6.x + v7.x));
                acc.y += ((v0.y + v1.y) + (v2.y + v3.y)) + ((v4.y + v5.y) + (v6.y + v7.y));
                acc.z += ((v0.z + v1.z) + (v2.z + v3.z)) + ((v4.z + v5.z) + (v6.z + v7.z));
                acc.w += ((v0.w + v1.w) + (v2.w + v3.w)) + ((v4.w + v5.w) + (v6.w + v7.w));
            }
            for (; j < deg; j++) {
                int s0 = csri[base + j];
                float4 a = *((const float4*)(hin + (size_t)s0 * H_) + lane);
                acc.x += a.x; acc.y += a.y; acc.z += a.z; acc.w += a.w;
            }
            float inv = 1.0f / fmaxf((float)deg, 1.0f);
            acc.x *= inv; acc.y *= inv; acc.z *= inv; acc.w *= inv;
        }
        *(float4*)&meanS[rl * 132 + lane * 4] = acc;
    }
    #pragma unroll
    for (int i = 0; i < 2; i++) {
        int idx = tid * 2 + i;
        int kk = idx >> 5, c = (idx & 31) * 4;
        *(float4*)&WSH(0, kk, c) = pw[i];
    }
    __syncthreads();

    float acc[4][8];
    #pragma unroll
    for (int i = 0; i < 4; i++)
        #pragma unroll
        for (int j = 0; j < 8; j++) acc[i][j] = 0.f;

    int cur = 0;
    float4 ph;

    // ---- first half: k = 0..127, A from meanS ----
    for (int kbi = 0; kbi < 8; kbi++) {
        int kwb = (kbi + 1) * 16;
        #pragma unroll
        for (int i = 0; i < 2; i++) {
            int idx = tid * 2 + i;
            int kk = idx >> 5, c = (idx & 31) * 4;
            int kw = kwb + kk;
            const float* ws = (kw < 128) ? (Wl + (size_t)kw * H_ + c)
                                         : (Wr + (size_t)(kw - 128) * H_ + c);
            pw[i] = *(const float4*)ws;
        }
        if (kbi == 7) {
            int r = tid >> 2, kc = (tid & 3) * 4;
            int row = row0 + r;
            ph = (row < nt) ? *(const float4*)(hin + (size_t)row * H_ + kc)
                            : make_float4(0.f, 0.f, 0.f, 0.f);
        }
        int kb = kbi * 16;
        #pragma unroll
        for (int kk = 0; kk < 16; kk++) {
            int kcol = kb + kk;
            float a[4];
            #pragma unroll
            for (int i = 0; i < 4; i++) a[i] = meanS[(rm + i) * 132 + kcol];
            float4 b0 = *(const float4*)&WSH(cur, kk, cn);
            float4 b1 = *(const float4*)&WSH(cur, kk, cn + 64);
            float b[8] = {b0.x, b0.y, b0.z, b0.w, b1.x, b1.y, b1.z, b1.w};
            #pragma unroll
            for (int i = 0; i < 4; i++)
                #pragma unroll
                for (int j = 0; j < 8; j++)
                    acc[i][j] += a[i] * b[j];
        }
        #pragma unroll
        for (int i = 0; i < 2; i++) {
            int idx = tid * 2 + i;
            int kk = idx >> 5, c = (idx & 31) * 4;
            *(float4*)&WSH(cur ^ 1, kk, c) = pw[i];
        }
        if (kbi == 7) {
            int r = tid >> 2, kc = (tid & 3) * 4;
            HSH(cur ^ 1, kc + 0, r) = ph.x;
            HSH(cur ^ 1, kc + 1, r) = ph.y;
            HSH(cur ^ 1, kc + 2, r) = ph.z;
            HSH(cur ^ 1, kc + 3, r) = ph.w;
        }
        __syncthreads();
        cur ^= 1;
    }

    // ---- second half: k = 128..255, A from Hsh ----
    for (int kbi = 8; kbi < 16; kbi++) {
        if (kbi < 15) {
            int kwb = (kbi + 1) * 16;
            int hb  = (kbi + 1 - 8) * 16;
            #pragma unroll
            for (int i = 0; i < 2; i++) {
                int idx = tid * 2 + i;
                int kk = idx >> 5, c = (idx & 31) * 4;
                pw[i] = *(const float4*)(Wr + (size_t)(kwb + kk - 128) * H_ + c);
            }
            int r = tid >> 2, kc = (tid & 3) * 4;
            int row = row0 + r;
            ph = (row < nt) ? *(const float4*)(hin + (size_t)row * H_ + hb + kc)
                            : make_float4(0.f, 0.f, 0.f, 0.f);
        }
        #pragma unroll
        for (int kk = 0; kk < 16; kk++) {
            float4 a0 = *(const float4*)&HSH(cur, kk, rm);
            float4 b0 = *(const float4*)&WSH(cur, kk, cn);
            float4 b1 = *(const float4*)&WSH(cur, kk, cn + 64);
            float a[4] = {a0.x, a0.y, a0.z, a0.w};
            float b[8] = {b0.x, b0.y, b0.z, b0.w, b1.x, b1.y, b1.z, b1.w};
            #pragma unroll
            for (int i = 0; i < 4; i++)
                #pragma unroll
                for (int j = 0; j < 8; j++)
                    acc[i][j] += a[i] * b[j];
        }
        if (kbi < 15) {
            #pragma unroll
            for (int i = 0; i < 2; i++) {
                int idx = tid * 2 + i;
                int kk = idx >> 5, c = (idx & 31) * 4;
                *(float4*)&WSH(cur ^ 1, kk, c) = pw[i];
            }
            int r = tid >> 2, kc = (tid & 3) * 4;
            HSH(cur ^ 1, kc + 0, r) = ph.x;
            HSH(cur ^ 1, kc + 1, r) = ph.y;
            HSH(cur ^ 1, kc + 2, r) = ph.z;
            HSH(cur ^ 1, kc + 3, r) = ph.w;
        }
        __syncthreads();
        cur ^= 1;
    }

    // ---- epilogue ----
    float4 bia0 = *(const float4*)&bb[cn];
    float4 bia1 = *(const float4*)&bb[cn + 64];
    float bias[8] = {bia0.x, bia0.y, bia0.z, bia0.w, bia1.x, bia1.y, bia1.z, bia1.w};
    float psum[8], psq[8];
    #pragma unroll
    for (int j = 0; j < 8; j++) { psum[j] = 0.f; psq[j] = 0.f; }
    #pragma unroll
    for (int i = 0; i < 4; i++) {
        int row = row0 + rm + i;
        if (row < nt) {
            float v[8];
            #pragma unroll
            for (int j = 0; j < 8; j++) {
                v[j] = acc[i][j] + bias[j];
                psum[j] += v[j];
                psq[j]  += v[j] * v[j];
            }
            *(float4*)(g_bufB + (size_t)row * H_ + cn)      = make_float4(v[0], v[1], v[2], v[3]);
            *(float4*)(g_bufB + (size_t)row * H_ + cn + 64) = make_float4(v[4], v[5], v[6], v[7]);
        }
    }
    __syncthreads();
    float* sumS = meanS;          // [16][128]
    float* sqS  = meanS + 2048;   // [16][128]
    #pragma unroll
    for (int j = 0; j < 4; j++) {
        sumS[ty * 128 + cn + j]      = psum[j];
        sumS[ty * 128 + cn + 64 + j] = psum[4 + j];
        sqS [ty * 128 + cn + j]      = psq[j];
        sqS [ty * 128 + cn + 64 + j] = psq[4 + j];
    }
    __syncthreads();
    if (tid < 128) {
        float s = 0.f, q = 0.f;
        #pragma unroll
        for (int t = 0; t < 16; t++) {
            s += sumS[t * 128 + tid];
            q += sqS [t * 128 + tid];
        }
        atomicAdd(&g_colsum[slot * H_ + tid], s);
        atomicAdd(&g_colsq [slot * H_ + tid], q);
    }
    #undef WSH
    #undef HSH
}

// ---------------- wide BN + ReLU + score ----------------
__global__ __launch_bounds__(256)
void bnscore_kernel(const float* __restrict__ gw, const float* __restrict__ be,
                    const float* __restrict__ p, int nt, float invnt, int slot) {
    int row = blockIdx.x * 8 + (threadIdx.x >> 5);
    int lane = threadIdx.x & 31;
    if (row >= nt) return;
    int c = lane * 4;
    float4 h  = *(const float4*)(g_bufB + (size_t)row * H_ + c);
    float4 cs = *(const float4*)&g_colsum[slot * H_ + c];
    float4 cq = *(const float4*)&g_colsq [slot * H_ + c];
    float4 gv = *(const float4*)&gw[c];
    float4 bv = *(const float4*)&be[c];
    float4 pv = *(const float4*)&p[c];
    float hh[4]  = {h.x, h.y, h.z, h.w};
    float css[4] = {cs.x, cs.y, cs.z, cs.w};
    float cqq[4] = {cq.x, cq.y, cq.z, cq.w};
    float gg[4]  = {gv.x, gv.y, gv.z, gv.w};
    float bbv[4] = {bv.x, bv.y, bv.z, bv.w};
    float pp[4]  = {pv.x, pv.y, pv.z, pv.w};
    float out[4];
    float dot = 0.f, pn = 0.f;
    #pragma unroll
    for (int j = 0; j < 4; j++) {
        float mu = css[j] * invnt;
        float var = cqq[j] * invnt - mu * mu;
        float r = rsqrtf(var + 1e-5f);
        float v = (hh[j] - mu) * r * gg[j] + bbv[j];
        v = fmaxf(v, 0.f);
        out[j] = v;
        dot += v * pp[j];
        pn  += pp[j] * pp[j];
    }
    *(float4*)(g_bufB + (size_t)row * H_ + c) = make_float4(out[0], out[1], out[2], out[3]);
    #pragma unroll
    for (int o = 16; o > 0; o >>= 1) {
        dot += __shfl_down_sync(0xffffffffu, dot, o);
        pn  += __shfl_down_sync(0xffffffffu, pn, o);
    }
    if (lane == 0) g_score[row] = dot * rsqrtf(pn);
}

// ---------------- mega: radix-select -> gather+readout -> CSR compaction (or MLP head) ----------------
__global__ __launch_bounds__(1024)
void mega_kernel(int b, int ncur, int ksel, int csrsel,
                 const float* __restrict__ Wd1, const float* __restrict__ bd1,
                 const float* __restrict__ Wd2, const float* __restrict__ bd2,
                 float* __restrict__ out) {
    extern __shared__ char smx[];
    float* s_score = (float*)(smx);            // [1024] scores by ORIGINAL id
    int*   s_perm  = (int*)(smx + 4096);       // [1024] new id -> old id
    int*   s_map   = (int*)(smx + 8192);       // [1024] old id -> new id (-1)
    int*   s_cnt   = (int*)(smx + 12288);
    int*   s_cur   = (int*)(smx + 16384);
    float* s_red   = (float*)(smx + 20480);    // 8192 floats: select scratch / readout partials / scan

    // old CSR buffers (read), new CSR buffers (write)
    const int* ocnt = csrsel ? g_cnt1 : g_cnt0;
    const int* ooff = csrsel ? g_off1 : g_off0;
    const int* ocsr = csrsel ? g_csr1 : g_csr0;
    int* ncnt = csrsel ? g_cnt0 : g_cnt1;
    int* noff = csrsel ? g_off0 : g_off1;
    int* ncsr = csrsel ? g_csr0 : g_csr1;

    int g = blockIdx.x, tid = threadIdx.x;
    int lane = tid & 31, wid = tid >> 5;
    int c = lane * 4;

    float myscore = (tid < ncur) ? g_score[g * ncur + tid] : -FLT_MAX;
    s_score[tid] = myscore;

    // orderable key: larger float -> larger uint; padding -> 0
    unsigned int key = 0u;
    if (tid < ncur) {
        unsigned int u = __float_as_uint(myscore);
        key = (u & 0x80000000u) ? ~u : (u | 0x80000000u);
    }

    // ---- radix select: k-th largest key T and tie budget R ----
    int* hist  = (int*)s_red;        // [256]
    int* hist2 = hist + 256;         // [256]
    int* wtot  = hist + 512;         // [8]
    int* s_sel = hist + 544;         // [2]
    unsigned int prefixK = 0u, pmask = 0u;
    int remaining = ksel;
    #pragma unroll
    for (int pass = 0; pass < 4; pass++) {
        int shift = 24 - pass * 8;
        if (tid < 256) hist[tid] = 0;
        __syncthreads();
        if ((key & pmask) == prefixK)
            atomicAdd(&hist[(key >> shift) & 255u], 1);
        __syncthreads();
        int inc = 0;
        if (tid < 256) {
            inc = hist[255 - tid];
            #pragma unroll
            for (int o = 1; o < 32; o <<= 1) {
                int t = __shfl_up_sync(0xffffffffu, inc, o);
                if (lane >= o) inc += t;
            }
            if (lane == 31) wtot[tid >> 5] = inc;
        }
        __syncthreads();
        if (tid < 256) {
            int w8 = tid >> 5, add = 0;
            for (int q = 0; q < w8; q++) add += wtot[q];
            hist2[tid] = inc + add;
        }
        __syncthreads();
        if (tid < 256) {
            int sfx = hist2[tid];
            int above = (tid == 0) ? 0 : hist2[tid - 1];
            if (sfx >= remaining && above < remaining) {
                s_sel[0] = 255 - tid;
                s_sel[1] = above;
            }
        }
        __syncthreads();
        prefixK |= ((unsigned int)s_sel[0]) << shift;
        pmask   |= 255u << shift;
        remaining -= s_sel[1];
        __syncthreads();
    }
    unsigned int T = prefixK;
    int R = remaining;

    // ---- stable compaction: new ids in original index order ----
    int strict = (key > T) ? 1 : 0;
    int tie    = (key == T) ? 1 : 0;
    int pk = strict | (tie << 16);
    int incs = pk;
    #pragma unroll
    for (int o = 1; o < 32; o <<= 1) {
        int t = __shfl_up_sync(0xffffffffu, incs, o);
        if (lane >= o) incs += t;
    }
    int* wsum = hist;
    if (lane == 31) wsum[wid] = incs;
    __syncthreads();
    if (wid == 0) {
        int ws = wsum[lane], wi = ws;
        #pragma unroll
        for (int o = 1; o < 32; o <<= 1) {
            int t = __shfl_up_sync(0xffffffffu, wi, o);
            if (lane >= o) wi += t;
        }
        wsum[lane] = wi - ws;
    }
    __syncthreads();
    int before = wsum[wid] + incs - pk;
    int sk_before  = before & 0xFFFF;
    int tie_before = before >> 16;
    int acc_f = strict | (tie & (tie_before < R ? 1 : 0));
    int newid = sk_before + (tie_before < R ? tie_before : R);
    s_map[tid] = acc_f ? newid : -1;
    if (acc_f) s_perm[newid] = tid;
    __syncthreads();

    // ---- gather + tanh gate + readout (skip bufA store on last block) ----
    float4 rsum = make_float4(0.f, 0.f, 0.f, 0.f);
    float4 rmax = make_float4(-FLT_MAX, -FLT_MAX, -FLT_MAX, -FLT_MAX);
    for (int nw = wid; nw < ksel; nw += 32) {
        int old = s_perm[nw];
        float t = tanhf(s_score[old]);
        float4 h = *(const float4*)(g_bufB + (size_t)(g * ncur + old) * H_ + c);
        h.x *= t; h.y *= t; h.z *= t; h.w *= t;
        if (b < 3) *(float4*)(g_bufA + (size_t)(g * ksel + nw) * H_ + c) = h;
        rsum.x += h.x; rsum.y += h.y; rsum.z += h.z; rsum.w += h.w;
        rmax.x = fmaxf(rmax.x, h.x); rmax.y = fmaxf(rmax.y, h.y);
        rmax.z = fmaxf(rmax.z, h.z); rmax.w = fmaxf(rmax.w, h.w);
    }
    __syncthreads();   // select scratch consumed
    *(float4*)&s_red[wid * 128 + c]        = rsum;
    *(float4*)&s_red[4096 + wid * 128 + c] = rmax;
    __syncthreads();
    if (tid < 128) {
        float s = 0.f, m = -FLT_MAX;
        #pragma unroll
        for (int w = 0; w < 32; w++) {
            s += s_red[w * 128 + tid];
            m = fmaxf(m, s_red[4096 + w * 128 + tid]);
        }
        g_flat[g * 1024 + b * 256 + tid]       = s;
        g_flat[g * 1024 + b * 256 + 128 + tid] = m;
    }
    __syncthreads();

    if (b < 3) {
        // ---- CSR-to-CSR compaction (old buf -> new buf) ----
        const int gbase = g * ncur;
        const int gk    = g * ksel;
        // phase A: count surviving neighbors per kept node (warp per node)
        for (int nw = wid; nw < ksel; nw += 32) {
            int old  = s_perm[nw];
            int deg  = ocnt[gbase + old];
            int base = ooff[gbase + old];
            int cnt = 0;
            for (int j0 = 0; j0 < deg; j0 += 32) {
                int j = j0 + lane;
                int m = -1;
                if (j < deg) m = s_map[ocsr[base + j] - gbase];
                cnt += __popc(__ballot_sync(0xffffffffu, m >= 0));
            }
            if (lane == 0) s_cnt[nw] = cnt;
        }
        __syncthreads();
        // phase B: block scan over s_cnt[0..ksel)
        int v = (tid < ksel) ? s_cnt[tid] : 0;
        int inc2 = v;
        #pragma unroll
        for (int o = 1; o < 32; o <<= 1) {
            int t = __shfl_up_sync(0xffffffffu, inc2, o);
            if (lane >= o) inc2 += t;
        }
        int* wsum2 = (int*)s_red;
        if (lane == 31) wsum2[wid] = inc2;
        __syncthreads();
        if (wid == 0) {
            int ws = wsum2[lane], wi = ws;
            #pragma unroll
            for (int o = 1; o < 32; o <<= 1) {
                int t = __shfl_up_sync(0xffffffffu, wi, o);
                if (lane >= o) wi += t;
            }
            wsum2[lane] = wi - ws;
        }
        __syncthreads();
        int ex = wsum2[wid] + inc2 - v;
        if (tid < ksel) {
            s_cur[tid] = ex;
            noff[gk + tid] = g * EPG + ex;
            ncnt[gk + tid] = v;
        }
        __syncthreads();
        // phase C: compacted fill (warp per node, ballot prefix keeps order)
        for (int nw = wid; nw < ksel; nw += 32) {
            int old  = s_perm[nw];
            int deg  = ocnt[gbase + old];
            int base = ooff[gbase + old];
            int nbase = g * EPG + s_cur[nw];
            int cum = 0;
            for (int j0 = 0; j0 < deg; j0 += 32) {
                int j = j0 + lane;
                int m = -1;
                if (j < deg) m = s_map[ocsr[base + j] - gbase];
                unsigned int mk = __ballot_sync(0xffffffffu, m >= 0);
                if (m >= 0) {
                    int pos = __popc(mk & ((1u << lane) - 1u));
                    ncsr[nbase + cum + pos] = gk + m;
                }
                cum += __popc(mk);
            }
        }
    } else {
        // ---- MLP head per graph ----
        float* a = (float*)s_map;
        a[tid] = g_flat[g * 1024 + tid];
        __syncthreads();
        float* hd = (float*)s_cnt;
        if (tid < 512) {
            float a0 = 0.f, a1 = 0.f, a2 = 0.f, a3 = 0.f;
            #pragma unroll 4
            for (int kk = 0; kk < 1024; kk += 4) {
                a0 += a[kk + 0] * Wd1[(kk + 0) * 512 + tid];
                a1 += a[kk + 1] * Wd1[(kk + 1) * 512 + tid];
                a2 += a[kk + 2] * Wd1[(kk + 2) * 512 + tid];
                a3 += a[kk + 3] * Wd1[(kk + 3) * 512 + tid];
            }
            hd[tid] = fmaxf(a0 + a1 + a2 + a3 + bd1[tid], 0.f);
        }
        __syncthreads();
        if (tid < 320) {
            int cc = tid >> 5, l = tid & 31;
            float acc = 0.f;
            for (int kk = l; kk < 512; kk += 32) acc += hd[kk] * Wd2[kk * 10 + cc];
            #pragma unroll
            for (int o = 16; o > 0; o >>= 1) acc += __shfl_down_sync(0xffffffffu, acc, o);
            if (l == 0) out[g * 10 + cc] = acc + bd2[cc];
        }
    }
}

// ---------------- launcher ----------------
extern "C" void kernel_launch(void* const* d_in, const int* in_sizes, int n_in,
                              void* d_out, int out_size) {
    const float* x  = (const float*)d_in[0];
    const int*   ei = (const int*)d_in[1];
    const float *Wl[4], *Wr[4], *bb[4], *gw[4], *be[4], *pp[4];
    int idx = 3;
    for (int b = 0; b < 4; b++) {
        Wl[b] = (const float*)d_in[idx++];
        Wr[b] = (const float*)d_in[idx++];
        bb[b] = (const float*)d_in[idx++];
        gw[b] = (const float*)d_in[idx++];
        be[b] = (const float*)d_in[idx++];
        pp[b] = (const float*)d_in[idx++];
    }
    const float* Wd1 = (const float*)d_in[27];
    const float* bd1 = (const float*)d_in[28];
    const float* Wd2 = (const float*)d_in[29];
    const float* bd2 = (const float*)d_in[30];
    float* out = (float*)d_out;

    cudaFuncSetAttribute(gemm_kernel, cudaFuncAttributeMaxDynamicSharedMemorySize,
                         SMEM_GEMM_BYTES);
    cudaFuncSetAttribute(mega_kernel, cudaFuncAttributeMaxDynamicSharedMemorySize,
                         MEGA_SMEM);

    csr0_kernel<<<G_, 1024>>>(ei);

    for (int b = 0; b < 4; b++) {
        int ncur = NCUR_H[b];
        int k    = KSEL_H[b];
        int nt   = G_ * ncur;
        int first = (b == 0) ? 1 : 0;
        int csrsel = b & 1;          // 0: read buf0, write buf1; 1: read buf1, write buf0

        gemm_kernel<<<(nt + 63) / 64, 256, SMEM_GEMM_BYTES>>>(
            x, first, b, csrsel, Wl[b], Wr[b], bb[b], nt);
        bnscore_kernel<<<(nt + 7) / 8, 256>>>(gw[b], be[b], pp[b], nt, 1.0f / (float)nt, b);
        mega_kernel<<<G_, 1024, MEGA_SMEM>>>(
            b, ncur, k, csrsel, Wd1, bd1, Wd2, bd2, out);
    }
}

// round 11
// speedup vs baseline: 1.0937x; 1.0937x over previous
#include <cuda_runtime.h>
#include <math.h>
#include <float.h>

// ---------------- problem constants ----------------
#define G_      32
#define EPG     16384                 // edges per graph
#define EDGES   (G_ * EPG)
#define H_      128
#define NT_MAX  32768

static const int NCUR_H[4] = {1024, 820, 656, 525};
static const int KSEL_H[4] = {820, 656, 525, 420};

// gemm smem: meanS 64x132 + W 2x16x128 + H 2x16x64  (floats)
#define SMEM_GEMM_BYTES ((64 * 132 + 2 * 16 * 128 + 2 * 16 * 64) * 4)
// mega smem: 3 x 4KB arrays + 32KB reduce/scratch region (+ head scratch)
#define MEGA_SMEM (5 * 4096 + 32 * 128 * 2 * 4)

// ---------------- device scratch ----------------
__device__ __align__(16) float g_bufA[NT_MAX * H_];  // pooled h (input of next block)
__device__ __align__(16) float g_bufB[NT_MAX * H_];  // conv out -> BN'd h
__device__ int   g_cnt0[NT_MAX];       // block-0 in-degree
__device__ int   g_off0[NT_MAX];       // block-0 absolute csr base
__device__ int   g_csr0[EDGES];        // block-0 neighbors (global old0 ids) grouped by dst
__device__ int   g_cmap[NT_MAX];       // old0 global id -> current pooled local id (-1)
__device__ int   g_cperm[NT_MAX];      // [g*1024 + pooled id] -> old0 local id
__device__ float g_score[NT_MAX];
__device__ __align__(16) float g_colsum[4 * H_];
__device__ __align__(16) float g_colsq [4 * H_];
__device__ float g_flat[G_ * 1024];

// ---------------- csr0: per-graph count+scan+fill for input edges ----------------
__global__ __launch_bounds__(1024)
void csr0_kernel(const int* __restrict__ ei) {
    __shared__ int cnt[1024], off[1024], cur[1024];
    __shared__ int wsum[32];
    int g = blockIdx.x, tid = threadIdx.x;
    int lane = tid & 31, wid = tid >> 5;
    cnt[tid] = 0;
    __syncthreads();
    const int* srcp = ei + g * EPG;
    const int* dstp = ei + EDGES + g * EPG;
    for (int e = tid; e < EPG; e += 1024)
        atomicAdd(&cnt[dstp[e] - (g << 10)], 1);
    __syncthreads();
    int v = cnt[tid];
    int inc = v;
    #pragma unroll
    for (int o = 1; o < 32; o <<= 1) {
        int t = __shfl_up_sync(0xffffffffu, inc, o);
        if (lane >= o) inc += t;
    }
    if (lane == 31) wsum[wid] = inc;
    __syncthreads();
    if (wid == 0) {
        int ws = wsum[lane], wi = ws;
        #pragma unroll
        for (int o = 1; o < 32; o <<= 1) {
            int t = __shfl_up_sync(0xffffffffu, wi, o);
            if (lane >= o) wi += t;
        }
        wsum[lane] = wi - ws;
    }
    __syncthreads();
    int ex = wsum[wid] + inc - v;
    off[tid] = ex;
    g_off0[g * 1024 + tid] = g * EPG + ex;
    g_cnt0[g * 1024 + tid] = v;
    cur[tid] = 0;
    __syncthreads();
    for (int e = tid; e < EPG; e += 1024) {
        int s = srcp[e];
        int d = dstp[e] - (g << 10);
        int pos = atomicAdd(&cur[d], 1);
        g_csr0[g * EPG + off[d] + pos] = s;
    }
    if (g == 0 && tid < 4 * H_) { g_colsum[tid] = 0.f; g_colsq[tid] = 0.f; }
}

// ---------------- fused gather-mean + GEMM + BN-stats (64-row tile) ----------------
// Block 0: gather directly from CSR0. Blocks >=1: gather CSR0 through cperm/cmap.
__global__ __launch_bounds__(256, 3)
void gemm_kernel(const float* __restrict__ x, int b, int ncur,
                 const float* __restrict__ Wl, const float* __restrict__ Wr,
                 const float* __restrict__ bb, int nt) {
    extern __shared__ float smem[];
    float* meanS = smem;                        // [64][132]
    float* WshB  = smem + 64 * 132;             // [2][16][128]
    float* HshB  = WshB + 2 * 16 * 128;         // [2][16][64]
    #define WSH(bf,k,c) WshB[(bf) * 2048 + (k) * 128 + (c)]
    #define HSH(bf,k,m) HshB[(bf) * 1024 + (k) * 64 + (m)]

    const int first = (b == 0);
    const float* hin = first ? x : g_bufA;
    int row0 = blockIdx.x * 64;
    int tid = threadIdx.x;
    int w = tid >> 5, lane = tid & 31;
    int tx = tid & 15, ty = tid >> 4;
    int rm = ty * 4, cn = tx * 4;

    // prefetch W block 0 behind the gather
    float4 pw[2];
    #pragma unroll
    for (int i = 0; i < 2; i++) {
        int idx = tid * 2 + i;
        int kk = idx >> 5, c = (idx & 31) * 4;
        pw[i] = *(const float4*)(Wl + (size_t)kk * H_ + c);
    }

    // ---- phase 1: gather means (8 rows per warp) ----
    for (int i = 0; i < 8; i++) {
        int rl = w * 8 + i;
        int row = row0 + rl;
        float4 acc = make_float4(0.f, 0.f, 0.f, 0.f);
        if (row < nt) {
            if (first) {
                int deg  = g_cnt0[row];
                int base = g_off0[row];
                int j = 0;
                for (; j + 8 <= deg; j += 8) {
                    int s0 = g_csr0[base + j + 0];
                    int s1 = g_csr0[base + j + 1];
                    int s2 = g_csr0[base + j + 2];
                    int s3 = g_csr0[base + j + 3];
                    int s4 = g_csr0[base + j + 4];
                    int s5 = g_csr0[base + j + 5];
                    int s6 = g_csr0[base + j + 6];
                    int s7 = g_csr0[base + j + 7];
                    float4 v0 = *((const float4*)(hin + (size_t)s0 * H_) + lane);
                    float4 v1 = *((const float4*)(hin + (size_t)s1 * H_) + lane);
                    float4 v2 = *((const float4*)(hin + (size_t)s2 * H_) + lane);
                    float4 v3 = *((const float4*)(hin + (size_t)s3 * H_) + lane);
                    float4 v4 = *((const float4*)(hin + (size_t)s4 * H_) + lane);
                    float4 v5 = *((const float4*)(hin + (size_t)s5 * H_) + lane);
                    float4 v6 = *((const float4*)(hin + (size_t)s6 * H_) + lane);
                    float4 v7 = *((const float4*)(hin + (size_t)s7 * H_) + lane);
                    acc.x += ((v0.x + v1.x) + (v2.x + v3.x)) + ((v4.x + v5.x) + (v6.x + v7.x));
                    acc.y += ((v0.y + v1.y) + (v2.y + v3.y)) + ((v4.y + v5.y) + (v6.y + v7.y));
                    acc.z += ((v0.z + v1.z) + (v2.z + v3.z)) + ((v4.z + v5.z) + (v6.z + v7.z));
                    acc.w += ((v0.w + v1.w) + (v2.w + v3.w)) + ((v4.w + v5.w) + (v6.w + v7.w));
                }
                for (; j < deg; j++) {
                    int s0 = g_csr0[base + j];
                    float4 a = *((const float4*)(hin + (size_t)s0 * H_) + lane);
                    acc.x += a.x; acc.y += a.y; acc.z += a.z; acc.w += a.w;
                }
                float inv = 1.0f / fmaxf((float)deg, 1.0f);
                acc.x *= inv; acc.y *= inv; acc.z *= inv; acc.w *= inv;
            } else {
                int g  = row / ncur;
                int r  = row - g * ncur;
                int old0 = g_cperm[(g << 10) + r];          // local old0 id
                int gi   = (g << 10) + old0;
                int deg0 = g_cnt0[gi];
                int base = g_off0[gi];
                size_t hb = (size_t)g * ncur;
                int cnt = 0;
                int j = 0;
                for (; j + 8 <= deg0; j += 8) {
                    int s0 = g_csr0[base + j + 0];
                    int s1 = g_csr0[base + j + 1];
                    int s2 = g_csr0[base + j + 2];
                    int s3 = g_csr0[base + j + 3];
                    int s4 = g_csr0[base + j + 4];
                    int s5 = g_csr0[base + j + 5];
                    int s6 = g_csr0[base + j + 6];
                    int s7 = g_csr0[base + j + 7];
                    int m0 = g_cmap[s0];
                    int m1 = g_cmap[s1];
                    int m2 = g_cmap[s2];
                    int m3 = g_cmap[s3];
                    int m4 = g_cmap[s4];
                    int m5 = g_cmap[s5];
                    int m6 = g_cmap[s6];
                    int m7 = g_cmap[s7];
                    if (m0 >= 0) { float4 v = *((const float4*)(hin + (hb + m0) * H_) + lane); acc.x += v.x; acc.y += v.y; acc.z += v.z; acc.w += v.w; cnt++; }
                    if (m1 >= 0) { float4 v = *((const float4*)(hin + (hb + m1) * H_) + lane); acc.x += v.x; acc.y += v.y; acc.z += v.z; acc.w += v.w; cnt++; }
                    if (m2 >= 0) { float4 v = *((const float4*)(hin + (hb + m2) * H_) + lane); acc.x += v.x; acc.y += v.y; acc.z += v.z; acc.w += v.w; cnt++; }
                    if (m3 >= 0) { float4 v = *((const float4*)(hin + (hb + m3) * H_) + lane); acc.x += v.x; acc.y += v.y; acc.z += v.z; acc.w += v.w; cnt++; }
                    if (m4 >= 0) { float4 v = *((const float4*)(hin + (hb + m4) * H_) + lane); acc.x += v.x; acc.y += v.y; acc.z += v.z; acc.w += v.w; cnt++; }
                    if (m5 >= 0) { float4 v = *((const float4*)(hin + (hb + m5) * H_) + lane); acc.x += v.x; acc.y += v.y; acc.z += v.z; acc.w += v.w; cnt++; }
                    if (m6 >= 0) { float4 v = *((const float4*)(hin + (hb + m6) * H_) + lane); acc.x += v.x; acc.y += v.y; acc.z += v.z; acc.w += v.w; cnt++; }
                    if (m7 >= 0) { float4 v = *((const float4*)(hin + (hb + m7) * H_) + lane); acc.x += v.x; acc.y += v.y; acc.z += v.z; acc.w += v.w; cnt++; }
                }
                for (; j < deg0; j++) {
                    int s0 = g_csr0[base + j];
                    int m0 = g_cmap[s0];
                    if (m0 >= 0) { float4 v = *((const float4*)(hin + (hb + m0) * H_) + lane); acc.x += v.x; acc.y += v.y; acc.z += v.z; acc.w += v.w; cnt++; }
                }
                float inv = 1.0f / fmaxf((float)cnt, 1.0f);
                acc.x *= inv; acc.y *= inv; acc.z *= inv; acc.w *= inv;
            }
        }
        *(float4*)&meanS[rl * 132 + lane * 4] = acc;
    }
    #pragma unroll
    for (int i = 0; i < 2; i++) {
        int idx = tid * 2 + i;
        int kk = idx >> 5, c = (idx & 31) * 4;
        *(float4*)&WSH(0, kk, c) = pw[i];
    }
    __syncthreads();

    float acc[4][8];
    #pragma unroll
    for (int i = 0; i < 4; i++)
        #pragma unroll
        for (int j = 0; j < 8; j++) acc[i][j] = 0.f;

    int cur = 0;
    float4 ph;

    // ---- first half: k = 0..127, A from meanS ----
    for (int kbi = 0; kbi < 8; kbi++) {
        int kwb = (kbi + 1) * 16;
        #pragma unroll
        for (int i = 0; i < 2; i++) {
            int idx = tid * 2 + i;
            int kk = idx >> 5, c = (idx & 31) * 4;
            int kw = kwb + kk;
            const float* ws = (kw < 128) ? (Wl + (size_t)kw * H_ + c)
                                         : (Wr + (size_t)(kw - 128) * H_ + c);
            pw[i] = *(const float4*)ws;
        }
        if (kbi == 7) {
            int r = tid >> 2, kc = (tid & 3) * 4;
            int row = row0 + r;
            ph = (row < nt) ? *(const float4*)(hin + (size_t)row * H_ + kc)
                            : make_float4(0.f, 0.f, 0.f, 0.f);
        }
        int kb = kbi * 16;
        #pragma unroll
        for (int kk = 0; kk < 16; kk++) {
            int kcol = kb + kk;
            float a[4];
            #pragma unroll
            for (int i = 0; i < 4; i++) a[i] = meanS[(rm + i) * 132 + kcol];
            float4 b0 = *(const float4*)&WSH(cur, kk, cn);
            float4 b1 = *(const float4*)&WSH(cur, kk, cn + 64);
            float bv[8] = {b0.x, b0.y, b0.z, b0.w, b1.x, b1.y, b1.z, b1.w};
            #pragma unroll
            for (int i = 0; i < 4; i++)
                #pragma unroll
                for (int j = 0; j < 8; j++)
                    acc[i][j] += a[i] * bv[j];
        }
        #pragma unroll
        for (int i = 0; i < 2; i++) {
            int idx = tid * 2 + i;
            int kk = idx >> 5, c = (idx & 31) * 4;
            *(float4*)&WSH(cur ^ 1, kk, c) = pw[i];
        }
        if (kbi == 7) {
            int r = tid >> 2, kc = (tid & 3) * 4;
            HSH(cur ^ 1, kc + 0, r) = ph.x;
            HSH(cur ^ 1, kc + 1, r) = ph.y;
            HSH(cur ^ 1, kc + 2, r) = ph.z;
            HSH(cur ^ 1, kc + 3, r) = ph.w;
        }
        __syncthreads();
        cur ^= 1;
    }

    // ---- second half: k = 128..255, A from Hsh ----
    for (int kbi = 8; kbi < 16; kbi++) {
        if (kbi < 15) {
            int kwb = (kbi + 1) * 16;
            int hb  = (kbi + 1 - 8) * 16;
            #pragma unroll
            for (int i = 0; i < 2; i++) {
                int idx = tid * 2 + i;
                int kk = idx >> 5, c = (idx & 31) * 4;
                pw[i] = *(const float4*)(Wr + (size_t)(kwb + kk - 128) * H_ + c);
            }
            int r = tid >> 2, kc = (tid & 3) * 4;
            int row = row0 + r;
            ph = (row < nt) ? *(const float4*)(hin + (size_t)row * H_ + hb + kc)
                            : make_float4(0.f, 0.f, 0.f, 0.f);
        }
        #pragma unroll
        for (int kk = 0; kk < 16; kk++) {
            float4 a0 = *(const float4*)&HSH(cur, kk, rm);
            float4 b0 = *(const float4*)&WSH(cur, kk, cn);
            float4 b1 = *(const float4*)&WSH(cur, kk, cn + 64);
            float a[4] = {a0.x, a0.y, a0.z, a0.w};
            float bv[8] = {b0.x, b0.y, b0.z, b0.w, b1.x, b1.y, b1.z, b1.w};
            #pragma unroll
            for (int i = 0; i < 4; i++)
                #pragma unroll
                for (int j = 0; j < 8; j++)
                    acc[i][j] += a[i] * bv[j];
        }
        if (kbi < 15) {
            #pragma unroll
            for (int i = 0; i < 2; i++) {
                int idx = tid * 2 + i;
                int kk = idx >> 5, c = (idx & 31) * 4;
                *(float4*)&WSH(cur ^ 1, kk, c) = pw[i];
            }
            int r = tid >> 2, kc = (tid & 3) * 4;
            HSH(cur ^ 1, kc + 0, r) = ph.x;
            HSH(cur ^ 1, kc + 1, r) = ph.y;
            HSH(cur ^ 1, kc + 2, r) = ph.z;
            HSH(cur ^ 1, kc + 3, r) = ph.w;
        }
        __syncthreads();
        cur ^= 1;
    }

    // ---- epilogue ----
    float4 bia0 = *(const float4*)&bb[cn];
    float4 bia1 = *(const float4*)&bb[cn + 64];
    float bias[8] = {bia0.x, bia0.y, bia0.z, bia0.w, bia1.x, bia1.y, bia1.z, bia1.w};
    float psum[8], psq[8];
    #pragma unroll
    for (int j = 0; j < 8; j++) { psum[j] = 0.f; psq[j] = 0.f; }
    #pragma unroll
    for (int i = 0; i < 4; i++) {
        int row = row0 + rm + i;
        if (row < nt) {
            float v[8];
            #pragma unroll
            for (int j = 0; j < 8; j++) {
                v[j] = acc[i][j] + bias[j];
                psum[j] += v[j];
                psq[j]  += v[j] * v[j];
            }
            *(float4*)(g_bufB + (size_t)row * H_ + cn)      = make_float4(v[0], v[1], v[2], v[3]);
            *(float4*)(g_bufB + (size_t)row * H_ + cn + 64) = make_float4(v[4], v[5], v[6], v[7]);
        }
    }
    __syncthreads();
    float* sumS = meanS;          // [16][128]
    float* sqS  = meanS + 2048;   // [16][128]
    #pragma unroll
    for (int j = 0; j < 4; j++) {
        sumS[ty * 128 + cn + j]      = psum[j];
        sumS[ty * 128 + cn + 64 + j] = psum[4 + j];
        sqS [ty * 128 + cn + j]      = psq[j];
        sqS [ty * 128 + cn + 64 + j] = psq[4 + j];
    }
    __syncthreads();
    if (tid < 128) {
        float s = 0.f, q = 0.f;
        #pragma unroll
        for (int t = 0; t < 16; t++) {
            s += sumS[t * 128 + tid];
            q += sqS [t * 128 + tid];
        }
        atomicAdd(&g_colsum[b * H_ + tid], s);
        atomicAdd(&g_colsq [b * H_ + tid], q);
    }
    #undef WSH
    #undef HSH
}

// ---------------- wide BN + ReLU + score ----------------
__global__ __launch_bounds__(256)
void bnscore_kernel(const float* __restrict__ gw, const float* __restrict__ be,
                    const float* __restrict__ p, int nt, float invnt, int slot) {
    int row = blockIdx.x * 8 + (threadIdx.x >> 5);
    int lane = threadIdx.x & 31;
    if (row >= nt) return;
    int c = lane * 4;
    float4 h  = *(const float4*)(g_bufB + (size_t)row * H_ + c);
    float4 cs = *(const float4*)&g_colsum[slot * H_ + c];
    float4 cq = *(const float4*)&g_colsq [slot * H_ + c];
    float4 gv = *(const float4*)&gw[c];
    float4 bv = *(const float4*)&be[c];
    float4 pv = *(const float4*)&p[c];
    float hh[4]  = {h.x, h.y, h.z, h.w};
    float css[4] = {cs.x, cs.y, cs.z, cs.w};
    float cqq[4] = {cq.x, cq.y, cq.z, cq.w};
    float gg[4]  = {gv.x, gv.y, gv.z, gv.w};
    float bbv[4] = {bv.x, bv.y, bv.z, bv.w};
    float pp[4]  = {pv.x, pv.y, pv.z, pv.w};
    float out[4];
    float dot = 0.f, pn = 0.f;
    #pragma unroll
    for (int j = 0; j < 4; j++) {
        float mu = css[j] * invnt;
        float var = cqq[j] * invnt - mu * mu;
        float r = rsqrtf(var + 1e-5f);
        float v = (hh[j] - mu) * r * gg[j] + bbv[j];
        v = fmaxf(v, 0.f);
        out[j] = v;
        dot += v * pp[j];
        pn  += pp[j] * pp[j];
    }
    *(float4*)(g_bufB + (size_t)row * H_ + c) = make_float4(out[0], out[1], out[2], out[3]);
    #pragma unroll
    for (int o = 16; o > 0; o >>= 1) {
        dot += __shfl_down_sync(0xffffffffu, dot, o);
        pn  += __shfl_down_sync(0xffffffffu, pn, o);
    }
    if (lane == 0) g_score[row] = dot * rsqrtf(pn);
}

// ---------------- mega: radix-select -> map compose -> gather+readout (or MLP head) ----------------
__global__ __launch_bounds__(1024)
void mega_kernel(int b, int ncur, int ksel,
                 const float* __restrict__ Wd1, const float* __restrict__ bd1,
                 const float* __restrict__ Wd2, const float* __restrict__ bd2,
                 float* __restrict__ out) {
    extern __shared__ char smx[];
    float* s_score = (float*)(smx);            // [1024] scores by current id
    int*   s_perm  = (int*)(smx + 4096);       // [1024] new id -> current id
    int*   s_map   = (int*)(smx + 8192);       // [1024] current id -> new id (-1)
    int*   s_cnt   = (int*)(smx + 12288);      // head scratch
    float* s_red   = (float*)(smx + 20480);    // 8192 floats: select scratch / readout partials

    int g = blockIdx.x, tid = threadIdx.x;
    int lane = tid & 31, wid = tid >> 5;
    int c = lane * 4;

    float myscore = (tid < ncur) ? g_score[g * ncur + tid] : -FLT_MAX;
    s_score[tid] = myscore;

    // orderable key: larger float -> larger uint; padding -> 0
    unsigned int key = 0u;
    if (tid < ncur) {
        unsigned int u = __float_as_uint(myscore);
        key = (u & 0x80000000u) ? ~u : (u | 0x80000000u);
    }

    // ---- radix select: k-th largest key T and tie budget R ----
    int* hist  = (int*)s_red;        // [256]
    int* hist2 = hist + 256;         // [256]
    int* wtot  = hist + 512;         // [8]
    int* s_sel = hist + 544;         // [2]
    unsigned int prefixK = 0u, pmask = 0u;
    int remaining = ksel;
    #pragma unroll
    for (int pass = 0; pass < 4; pass++) {
        int shift = 24 - pass * 8;
        if (tid < 256) hist[tid] = 0;
        __syncthreads();
        if ((key & pmask) == prefixK)
            atomicAdd(&hist[(key >> shift) & 255u], 1);
        __syncthreads();
        int inc = 0;
        if (tid < 256) {
            inc = hist[255 - tid];
            #pragma unroll
            for (int o = 1; o < 32; o <<= 1) {
                int t = __shfl_up_sync(0xffffffffu, inc, o);
                if (lane >= o) inc += t;
            }
            if (lane == 31) wtot[tid >> 5] = inc;
        }
        __syncthreads();
        if (tid < 256) {
            int w8 = tid >> 5, add = 0;
            for (int q = 0; q < w8; q++) add += wtot[q];
            hist2[tid] = inc + add;
        }
        __syncthreads();
        if (tid < 256) {
            int sfx = hist2[tid];
            int above = (tid == 0) ? 0 : hist2[tid - 1];
            if (sfx >= remaining && above < remaining) {
                s_sel[0] = 255 - tid;
                s_sel[1] = above;
            }
        }
        __syncthreads();
        prefixK |= ((unsigned int)s_sel[0]) << shift;
        pmask   |= 255u << shift;
        remaining -= s_sel[1];
        __syncthreads();
    }
    unsigned int T = prefixK;
    int R = remaining;

    // ---- stable compaction: new ids in current-index order ----
    int strict = (key > T) ? 1 : 0;
    int tie    = (key == T) ? 1 : 0;
    int pk = strict | (tie << 16);
    int incs = pk;
    #pragma unroll
    for (int o = 1; o < 32; o <<= 1) {
        int t = __shfl_up_sync(0xffffffffu, incs, o);
        if (lane >= o) incs += t;
    }
    int* wsum = hist;
    if (lane == 31) wsum[wid] = incs;
    __syncthreads();
    if (wid == 0) {
        int ws = wsum[lane], wi = ws;
        #pragma unroll
        for (int o = 1; o < 32; o <<= 1) {
            int t = __shfl_up_sync(0xffffffffu, wi, o);
            if (lane >= o) wi += t;
        }
        wsum[lane] = wi - ws;
    }
    __syncthreads();
    int before = wsum[wid] + incs - pk;
    int sk_before  = before & 0xFFFF;
    int tie_before = before >> 16;
    int acc_f = strict | (tie & (tie_before < R ? 1 : 0));
    int newid = sk_before + (tie_before < R ? tie_before : R);
    s_map[tid] = acc_f ? newid : -1;
    if (acc_f) s_perm[newid] = tid;
    __syncthreads();

    // ---- compose old0 -> pooled map (b < 3 only; consumed by next gemm) ----
    if (b < 3) {
        int gi = (g << 10) + tid;
        int nn;
        if (b == 0) {
            nn = s_map[tid];
        } else {
            int prev = g_cmap[gi];
            nn = (prev >= 0) ? s_map[prev] : -1;
        }
        g_cmap[gi] = nn;
        if (nn >= 0) g_cperm[(g << 10) + nn] = tid;
    }

    // ---- gather + tanh gate + readout (skip bufA store on last block) ----
    float4 rsum = make_float4(0.f, 0.f, 0.f, 0.f);
    float4 rmax = make_float4(-FLT_MAX, -FLT_MAX, -FLT_MAX, -FLT_MAX);
    for (int nw = wid; nw < ksel; nw += 32) {
        int old = s_perm[nw];
        float t = tanhf(s_score[old]);
        float4 h = *(const float4*)(g_bufB + (size_t)(g * ncur + old) * H_ + c);
        h.x *= t; h.y *= t; h.z *= t; h.w *= t;
        if (b < 3) *(float4*)(g_bufA + (size_t)(g * ksel + nw) * H_ + c) = h;
        rsum.x += h.x; rsum.y += h.y; rsum.z += h.z; rsum.w += h.w;
        rmax.x = fmaxf(rmax.x, h.x); rmax.y = fmaxf(rmax.y, h.y);
        rmax.z = fmaxf(rmax.z, h.z); rmax.w = fmaxf(rmax.w, h.w);
    }
    __syncthreads();   // select scratch consumed
    *(float4*)&s_red[wid * 128 + c]        = rsum;
    *(float4*)&s_red[4096 + wid * 128 + c] = rmax;
    __syncthreads();
    if (tid < 128) {
        float s = 0.f, m = -FLT_MAX;
        #pragma unroll
        for (int w = 0; w < 32; w++) {
            s += s_red[w * 128 + tid];
            m = fmaxf(m, s_red[4096 + w * 128 + tid]);
        }
        g_flat[g * 1024 + b * 256 + tid]       = s;
        g_flat[g * 1024 + b * 256 + 128 + tid] = m;
    }

    if (b == 3) {
        // ---- MLP head per graph ----
        __syncthreads();
        float* a = (float*)s_map;
        a[tid] = g_flat[g * 1024 + tid];
        __syncthreads();
        float* hd = (float*)s_cnt;
        if (tid < 512) {
            float a0 = 0.f, a1 = 0.f, a2 = 0.f, a3 = 0.f;
            #pragma unroll 4
            for (int kk = 0; kk < 1024; kk += 4) {
                a0 += a[kk + 0] * Wd1[(kk + 0) * 512 + tid];
                a1 += a[kk + 1] * Wd1[(kk + 1) * 512 + tid];
                a2 += a[kk + 2] * Wd1[(kk + 2) * 512 + tid];
                a3 += a[kk + 3] * Wd1[(kk + 3) * 512 + tid];
            }
            hd[tid] = fmaxf(a0 + a1 + a2 + a3 + bd1[tid], 0.f);
        }
        __syncthreads();
        if (tid < 320) {
            int cc = tid >> 5, l = tid & 31;
            float acc = 0.f;
            for (int kk = l; kk < 512; kk += 32) acc += hd[kk] * Wd2[kk * 10 + cc];
            #pragma unroll
            for (int o = 16; o > 0; o >>= 1) acc += __shfl_down_sync(0xffffffffu, acc, o);
            if (l == 0) out[g * 10 + cc] = acc + bd2[cc];
        }
    }
}

// ---------------- launcher ----------------
extern "C" void kernel_launch(void* const* d_in, const int* in_sizes, int n_in,
                              void* d_out, int out_size) {
    const float* x  = (const float*)d_in[0];
    const int*   ei = (const int*)d_in[1];
    const float *Wl[4], *Wr[4], *bb[4], *gw[4], *be[4], *pp[4];
    int idx = 3;
    for (int b = 0; b < 4; b++) {
        Wl[b] = (const float*)d_in[idx++];
        Wr[b] = (const float*)d_in[idx++];
        bb[b] = (const float*)d_in[idx++];
        gw[b] = (const float*)d_in[idx++];
        be[b] = (const float*)d_in[idx++];
        pp[b] = (const float*)d_in[idx++];
    }
    const float* Wd1 = (const float*)d_in[27];
    const float* bd1 = (const float*)d_in[28];
    const float* Wd2 = (const float*)d_in[29];
    const float* bd2 = (const float*)d_in[30];
    float* out = (float*)d_out;

    cudaFuncSetAttribute(gemm_kernel, cudaFuncAttributeMaxDynamicSharedMemorySize,
                         SMEM_GEMM_BYTES);
    cudaFuncSetAttribute(mega_kernel, cudaFuncAttributeMaxDynamicSharedMemorySize,
                         MEGA_SMEM);

    csr0_kernel<<<G_, 1024>>>(ei);

    for (int b = 0; b < 4; b++) {
        int ncur = NCUR_H[b];
        int k    = KSEL_H[b];
        int nt   = G_ * ncur;

        gemm_kernel<<<(nt + 63) / 64, 256, SMEM_GEMM_BYTES>>>(
            x, b, ncur, Wl[b], Wr[b], bb[b], nt);
        bnscore_kernel<<<(nt + 7) / 8, 256>>>(gw[b], be[b], pp[b], nt, 1.0f / (float)nt, b);
        mega_kernel<<<G_, 1024, MEGA_SMEM>>>(
            b, ncur, k, Wd1, bd1, Wd2, bd2, out);
    }
}

// round 12
// speedup vs baseline: 1.1267x; 1.0302x over previous
#include <cuda_runtime.h>
#include <math.h>
#include <float.h>

// ---------------- problem constants ----------------
#define G_      32
#define EPG     16384                 // edges per graph
#define EDGES   (G_ * EPG)
#define H_      128
#define NT_MAX  32768

static const int NCUR_H[4] = {1024, 820, 656, 525};
static const int KSEL_H[4] = {820, 656, 525, 420};

// gemm smem: meanS 64x132 + W 2x16x128 + H 2x16x64  (floats)
#define SMEM_GEMM_BYTES ((64 * 132 + 2 * 16 * 128 + 2 * 16 * 64) * 4)
// mega smem: arrays + reduce/scratch
#define MEGA_SMEM (5 * 4096 + 32 * 128 * 2 * 4)

// ---------------- device scratch (double-buffered pooled CSR) ----------------
__device__ __align__(16) float g_bufA[NT_MAX * H_];  // pooled h (input of next block)
__device__ __align__(16) float g_bufB[NT_MAX * H_];  // conv out -> BN'd h
__device__ int   g_cnt0[NT_MAX],  g_cnt1[NT_MAX];    // surviving in-degree per node
__device__ int   g_off0[NT_MAX],  g_off1[NT_MAX];    // absolute csr base per node
__device__ int   g_csrA[EDGES],   g_csrB[EDGES];     // neighbor global ids grouped by dst
__device__ int   g_mapG[NT_MAX];   // current global id -> new local id (-1)
__device__ int   g_permG[NT_MAX];  // new global id (g*ksel+nw) -> old current local id
__device__ float g_score[NT_MAX];
__device__ __align__(16) float g_colsum[4 * H_];
__device__ __align__(16) float g_colsq [4 * H_];
__device__ float g_flat[G_ * 1024];

// ---------------- csr0: per-graph count+scan+fill for input edges (buffer 0 / csrA) ----------------
__global__ __launch_bounds__(1024)
void csr0_kernel(const int* __restrict__ ei) {
    __shared__ int cnt[1024], off[1024], cur[1024];
    __shared__ int wsum[32];
    int g = blockIdx.x, tid = threadIdx.x;
    int lane = tid & 31, wid = tid >> 5;
    cnt[tid] = 0;
    __syncthreads();
    const int* srcp = ei + g * EPG;
    const int* dstp = ei + EDGES + g * EPG;
    for (int e = tid; e < EPG; e += 1024)
        atomicAdd(&cnt[dstp[e] - (g << 10)], 1);
    __syncthreads();
    int v = cnt[tid];
    int inc = v;
    #pragma unroll
    for (int o = 1; o < 32; o <<= 1) {
        int t = __shfl_up_sync(0xffffffffu, inc, o);
        if (lane >= o) inc += t;
    }
    if (lane == 31) wsum[wid] = inc;
    __syncthreads();
    if (wid == 0) {
        int ws = wsum[lane], wi = ws;
        #pragma unroll
        for (int o = 1; o < 32; o <<= 1) {
            int t = __shfl_up_sync(0xffffffffu, wi, o);
            if (lane >= o) wi += t;
        }
        wsum[lane] = wi - ws;
    }
    __syncthreads();
    int ex = wsum[wid] + inc - v;
    off[tid] = ex;
    g_off0[g * 1024 + tid] = g * EPG + ex;
    g_cnt0[g * 1024 + tid] = v;
    cur[tid] = 0;
    __syncthreads();
    for (int e = tid; e < EPG; e += 1024) {
        int s = srcp[e];                      // global node id
        int d = dstp[e] - (g << 10);
        int pos = atomicAdd(&cur[d], 1);
        g_csrA[g * EPG + off[d] + pos] = s;
    }
    if (g == 0 && tid < 4 * H_) { g_colsum[tid] = 0.f; g_colsq[tid] = 0.f; }
}

// ---------------- wide CSR compaction: old pooled CSR -> new pooled CSR ----------------
// warp per new node; new node inherits old node's CSR slot (capacity >= surviving degree)
__global__ __launch_bounds__(256)
void compact_kernel(int ncur, int ksel, int sel) {
    const int* ocnt = sel ? g_cnt1 : g_cnt0;
    const int* ooff = sel ? g_off1 : g_off0;
    const int* ocsr = sel ? g_csrB : g_csrA;
    int* ncnt = sel ? g_cnt0 : g_cnt1;
    int* noff = sel ? g_off0 : g_off1;
    int* ncsr = sel ? g_csrA : g_csrB;

    int n = (blockIdx.x * blockDim.x + threadIdx.x) >> 5;
    int lane = threadIdx.x & 31;
    if (n >= G_ * ksel) return;
    int g = n / ksel;
    int og = g * ncur + g_permG[n];           // old current global id
    int deg  = ocnt[og];
    int base = ooff[og];
    int gk = g * ksel;
    int cum = 0;
    for (int j0 = 0; j0 < deg; j0 += 32) {
        int j = j0 + lane;
        int m = -1;
        if (j < deg) m = g_mapG[ocsr[base + j]];
        unsigned int mk = __ballot_sync(0xffffffffu, m >= 0);
        if (m >= 0) {
            int pos = __popc(mk & ((1u << lane) - 1u));
            ncsr[base + cum + pos] = gk + m;
        }
        cum += __popc(mk);
    }
    if (lane == 0) { ncnt[n] = cum; noff[n] = base; }
}

// ---------------- fused gather-mean + GEMM + BN-stats (64-row tile) ----------------
__global__ __launch_bounds__(256, 3)
void gemm_kernel(const float* __restrict__ x, int first, int slot, int sel,
                 const float* __restrict__ Wl, const float* __restrict__ Wr,
                 const float* __restrict__ bb, int nt) {
    extern __shared__ float smem[];
    float* meanS = smem;                        // [64][132]
    float* WshB  = smem + 64 * 132;             // [2][16][128]
    float* HshB  = WshB + 2 * 16 * 128;         // [2][16][64]
    #define WSH(bf,k,c) WshB[(bf) * 2048 + (k) * 128 + (c)]
    #define HSH(bf,k,m) HshB[(bf) * 1024 + (k) * 64 + (m)]

    const int* cnti = sel ? g_cnt1 : g_cnt0;
    const int* offi = sel ? g_off1 : g_off0;
    const int* csri = sel ? g_csrB : g_csrA;

    const float* hin = first ? x : g_bufA;
    int row0 = blockIdx.x * 64;
    int tid = threadIdx.x;
    int w = tid >> 5, lane = tid & 31;
    int tx = tid & 15, ty = tid >> 4;
    int rm = ty * 4, cn = tx * 4;

    // prefetch W block 0 behind the gather
    float4 pw[2];
    #pragma unroll
    for (int i = 0; i < 2; i++) {
        int idx = tid * 2 + i;
        int kk = idx >> 5, c = (idx & 31) * 4;
        pw[i] = *(const float4*)(Wl + (size_t)kk * H_ + c);
    }

    // ---- phase 1: gather means (8 rows per warp, 8 loads in flight) ----
    for (int i = 0; i < 8; i++) {
        int rl = w * 8 + i;
        int row = row0 + rl;
        float4 acc = make_float4(0.f, 0.f, 0.f, 0.f);
        if (row < nt) {
            int deg  = cnti[row];
            int base = offi[row];
            int j = 0;
            for (; j + 8 <= deg; j += 8) {
                int s0 = csri[base + j + 0];
                int s1 = csri[base + j + 1];
                int s2 = csri[base + j + 2];
                int s3 = csri[base + j + 3];
                int s4 = csri[base + j + 4];
                int s5 = csri[base + j + 5];
                int s6 = csri[base + j + 6];
                int s7 = csri[base + j + 7];
                float4 v0 = *((const float4*)(hin + (size_t)s0 * H_) + lane);
                float4 v1 = *((const float4*)(hin + (size_t)s1 * H_) + lane);
                float4 v2 = *((const float4*)(hin + (size_t)s2 * H_) + lane);
                float4 v3 = *((const float4*)(hin + (size_t)s3 * H_) + lane);
                float4 v4 = *((const float4*)(hin + (size_t)s4 * H_) + lane);
                float4 v5 = *((const float4*)(hin + (size_t)s5 * H_) + lane);
                float4 v6 = *((const float4*)(hin + (size_t)s6 * H_) + lane);
                float4 v7 = *((const float4*)(hin + (size_t)s7 * H_) + lane);
                acc.x += ((v0.x + v1.x) + (v2.x + v3.x)) + ((v4.x + v5.x) + (v6.x + v7.x));
                acc.y += ((v0.y + v1.y) + (v2.y + v3.y)) + ((v4.y + v5.y) + (v6.y + v7.y));
                acc.z += ((v0.z + v1.z) + (v2.z + v3.z)) + ((v4.z + v5.z) + (v6.z + v7.z));
                acc.w += ((v0.w + v1.w) + (v2.w + v3.w)) + ((v4.w + v5.w) + (v6.w + v7.w));
            }
            for (; j < deg; j++) {
                int s0 = csri[base + j];
                float4 a = *((const float4*)(hin + (size_t)s0 * H_) + lane);
                acc.x += a.x; acc.y += a.y; acc.z += a.z; acc.w += a.w;
            }
            float inv = 1.0f / fmaxf((float)deg, 1.0f);
            acc.x *= inv; acc.y *= inv; acc.z *= inv; acc.w *= inv;
        }
        *(float4*)&meanS[rl * 132 + lane * 4] = acc;
    }
    #pragma unroll
    for (int i = 0; i < 2; i++) {
        int idx = tid * 2 + i;
        int kk = idx >> 5, c = (idx & 31) * 4;
        *(float4*)&WSH(0, kk, c) = pw[i];
    }
    __syncthreads();

    float acc[4][8];
    #pragma unroll
    for (int i = 0; i < 4; i++)
        #pragma unroll
        for (int j = 0; j < 8; j++) acc[i][j] = 0.f;

    int cur = 0;
    float4 ph;

    // ---- first half: k = 0..127, A from meanS ----
    for (int kbi = 0; kbi < 8; kbi++) {
        int kwb = (kbi + 1) * 16;
        #pragma unroll
        for (int i = 0; i < 2; i++) {
            int idx = tid * 2 + i;
            int kk = idx >> 5, c = (idx & 31) * 4;
            int kw = kwb + kk;
            const float* ws = (kw < 128) ? (Wl + (size_t)kw * H_ + c)
                                         : (Wr + (size_t)(kw - 128) * H_ + c);
            pw[i] = *(const float4*)ws;
        }
        if (kbi == 7) {
            int r = tid >> 2, kc = (tid & 3) * 4;
            int row = row0 + r;
            ph = (row < nt) ? *(const float4*)(hin + (size_t)row * H_ + kc)
                            : make_float4(0.f, 0.f, 0.f, 0.f);
        }
        int kb = kbi * 16;
        #pragma unroll
        for (int kk = 0; kk < 16; kk++) {
            int kcol = kb + kk;
            float a[4];
            #pragma unroll
            for (int i = 0; i < 4; i++) a[i] = meanS[(rm + i) * 132 + kcol];
            float4 b0 = *(const float4*)&WSH(cur, kk, cn);
            float4 b1 = *(const float4*)&WSH(cur, kk, cn + 64);
            float bv[8] = {b0.x, b0.y, b0.z, b0.w, b1.x, b1.y, b1.z, b1.w};
            #pragma unroll
            for (int i = 0; i < 4; i++)
                #pragma unroll
                for (int j = 0; j < 8; j++)
                    acc[i][j] += a[i] * bv[j];
        }
        #pragma unroll
        for (int i = 0; i < 2; i++) {
            int idx = tid * 2 + i;
            int kk = idx >> 5, c = (idx & 31) * 4;
            *(float4*)&WSH(cur ^ 1, kk, c) = pw[i];
        }
        if (kbi == 7) {
            int r = tid >> 2, kc = (tid & 3) * 4;
            HSH(cur ^ 1, kc + 0, r) = ph.x;
            HSH(cur ^ 1, kc + 1, r) = ph.y;
            HSH(cur ^ 1, kc + 2, r) = ph.z;
            HSH(cur ^ 1, kc + 3, r) = ph.w;
        }
        __syncthreads();
        cur ^= 1;
    }

    // ---- second half: k = 128..255, A from Hsh ----
    for (int kbi = 8; kbi < 16; kbi++) {
        if (kbi < 15) {
            int kwb = (kbi + 1) * 16;
            int hb  = (kbi + 1 - 8) * 16;
            #pragma unroll
            for (int i = 0; i < 2; i++) {
                int idx = tid * 2 + i;
                int kk = idx >> 5, c = (idx & 31) * 4;
                pw[i] = *(const float4*)(Wr + (size_t)(kwb + kk - 128) * H_ + c);
            }
            int r = tid >> 2, kc = (tid & 3) * 4;
            int row = row0 + r;
            ph = (row < nt) ? *(const float4*)(hin + (size_t)row * H_ + hb + kc)
                            : make_float4(0.f, 0.f, 0.f, 0.f);
        }
        #pragma unroll
        for (int kk = 0; kk < 16; kk++) {
            float4 a0 = *(const float4*)&HSH(cur, kk, rm);
            float4 b0 = *(const float4*)&WSH(cur, kk, cn);
            float4 b1 = *(const float4*)&WSH(cur, kk, cn + 64);
            float a[4] = {a0.x, a0.y, a0.z, a0.w};
            float bv[8] = {b0.x, b0.y, b0.z, b0.w, b1.x, b1.y, b1.z, b1.w};
            #pragma unroll
            for (int i = 0; i < 4; i++)
                #pragma unroll
                for (int j = 0; j < 8; j++)
                    acc[i][j] += a[i] * bv[j];
        }
        if (kbi < 15) {
            #pragma unroll
            for (int i = 0; i < 2; i++) {
                int idx = tid * 2 + i;
                int kk = idx >> 5, c = (idx & 31) * 4;
                *(float4*)&WSH(cur ^ 1, kk, c) = pw[i];
            }
            int r = tid >> 2, kc = (tid & 3) * 4;
            HSH(cur ^ 1, kc + 0, r) = ph.x;
            HSH(cur ^ 1, kc + 1, r) = ph.y;
            HSH(cur ^ 1, kc + 2, r) = ph.z;
            HSH(cur ^ 1, kc + 3, r) = ph.w;
        }
        __syncthreads();
        cur ^= 1;
    }

    // ---- epilogue ----
    float4 bia0 = *(const float4*)&bb[cn];
    float4 bia1 = *(const float4*)&bb[cn + 64];
    float bias[8] = {bia0.x, bia0.y, bia0.z, bia0.w, bia1.x, bia1.y, bia1.z, bia1.w};
    float psum[8], psq[8];
    #pragma unroll
    for (int j = 0; j < 8; j++) { psum[j] = 0.f; psq[j] = 0.f; }
    #pragma unroll
    for (int i = 0; i < 4; i++) {
        int row = row0 + rm + i;
        if (row < nt) {
            float v[8];
            #pragma unroll
            for (int j = 0; j < 8; j++) {
                v[j] = acc[i][j] + bias[j];
                psum[j] += v[j];
                psq[j]  += v[j] * v[j];
            }
            *(float4*)(g_bufB + (size_t)row * H_ + cn)      = make_float4(v[0], v[1], v[2], v[3]);
            *(float4*)(g_bufB + (size_t)row * H_ + cn + 64) = make_float4(v[4], v[5], v[6], v[7]);
        }
    }
    __syncthreads();
    float* sumS = meanS;          // [16][128]
    float* sqS  = meanS + 2048;   // [16][128]
    #pragma unroll
    for (int j = 0; j < 4; j++) {
        sumS[ty * 128 + cn + j]      = psum[j];
        sumS[ty * 128 + cn + 64 + j] = psum[4 + j];
        sqS [ty * 128 + cn + j]      = psq[j];
        sqS [ty * 128 + cn + 64 + j] = psq[4 + j];
    }
    __syncthreads();
    if (tid < 128) {
        float s = 0.f, q = 0.f;
        #pragma unroll
        for (int t = 0; t < 16; t++) {
            s += sumS[t * 128 + tid];
            q += sqS [t * 128 + tid];
        }
        atomicAdd(&g_colsum[slot * H_ + tid], s);
        atomicAdd(&g_colsq [slot * H_ + tid], q);
    }
    #undef WSH
    #undef HSH
}

// ---------------- wide BN + ReLU + score ----------------
__global__ __launch_bounds__(256)
void bnscore_kernel(const float* __restrict__ gw, const float* __restrict__ be,
                    const float* __restrict__ p, int nt, float invnt, int slot) {
    int row = blockIdx.x * 8 + (threadIdx.x >> 5);
    int lane = threadIdx.x & 31;
    if (row >= nt) return;
    int c = lane * 4;
    float4 h  = *(const float4*)(g_bufB + (size_t)row * H_ + c);
    float4 cs = *(const float4*)&g_colsum[slot * H_ + c];
    float4 cq = *(const float4*)&g_colsq [slot * H_ + c];
    float4 gv = *(const float4*)&gw[c];
    float4 bv = *(const float4*)&be[c];
    float4 pv = *(const float4*)&p[c];
    float hh[4]  = {h.x, h.y, h.z, h.w};
    float css[4] = {cs.x, cs.y, cs.z, cs.w};
    float cqq[4] = {cq.x, cq.y, cq.z, cq.w};
    float gg[4]  = {gv.x, gv.y, gv.z, gv.w};
    float bbv[4] = {bv.x, bv.y, bv.z, bv.w};
    float pp[4]  = {pv.x, pv.y, pv.z, pv.w};
    float out[4];
    float dot = 0.f, pn = 0.f;
    #pragma unroll
    for (int j = 0; j < 4; j++) {
        float mu = css[j] * invnt;
        float var = cqq[j] * invnt - mu * mu;
        float r = rsqrtf(var + 1e-5f);
        float v = (hh[j] - mu) * r * gg[j] + bbv[j];
        v = fmaxf(v, 0.f);
        out[j] = v;
        dot += v * pp[j];
        pn  += pp[j] * pp[j];
    }
    *(float4*)(g_bufB + (size_t)row * H_ + c) = make_float4(out[0], out[1], out[2], out[3]);
    #pragma unroll
    for (int o = 16; o > 0; o >>= 1) {
        dot += __shfl_down_sync(0xffffffffu, dot, o);
        pn  += __shfl_down_sync(0xffffffffu, pn, o);
    }
    if (lane == 0) g_score[row] = dot * rsqrtf(pn);
}

// ---------------- mega: radix-select -> publish map/perm -> gather+readout (or MLP head) ----------------
__global__ __launch_bounds__(1024)
void mega_kernel(int b, int ncur, int ksel,
                 const float* __restrict__ Wd1, const float* __restrict__ bd1,
                 const float* __restrict__ Wd2, const float* __restrict__ bd2,
                 float* __restrict__ out) {
    extern __shared__ char smx[];
    float* s_score = (float*)(smx);            // [1024]
    int*   s_perm  = (int*)(smx + 4096);       // [1024] new id -> current id
    int*   s_map   = (int*)(smx + 8192);       // [1024] current id -> new id (-1)
    int*   s_cnt   = (int*)(smx + 12288);      // head scratch
    float* s_red   = (float*)(smx + 20480);    // 8192 floats

    int g = blockIdx.x, tid = threadIdx.x;
    int lane = tid & 31, wid = tid >> 5;
    int c = lane * 4;

    float myscore = (tid < ncur) ? g_score[g * ncur + tid] : -FLT_MAX;
    s_score[tid] = myscore;

    unsigned int key = 0u;
    if (tid < ncur) {
        unsigned int u = __float_as_uint(myscore);
        key = (u & 0x80000000u) ? ~u : (u | 0x80000000u);
    }

    // ---- radix select ----
    int* hist  = (int*)s_red;
    int* hist2 = hist + 256;
    int* wtot  = hist + 512;
    int* s_sel = hist + 544;
    unsigned int prefixK = 0u, pmask = 0u;
    int remaining = ksel;
    #pragma unroll
    for (int pass = 0; pass < 4; pass++) {
        int shift = 24 - pass * 8;
        if (tid < 256) hist[tid] = 0;
        __syncthreads();
        if ((key & pmask) == prefixK)
            atomicAdd(&hist[(key >> shift) & 255u], 1);
        __syncthreads();
        int inc = 0;
        if (tid < 256) {
            inc = hist[255 - tid];
            #pragma unroll
            for (int o = 1; o < 32; o <<= 1) {
                int t = __shfl_up_sync(0xffffffffu, inc, o);
                if (lane >= o) inc += t;
            }
            if (lane == 31) wtot[tid >> 5] = inc;
        }
        __syncthreads();
        if (tid < 256) {
            int w8 = tid >> 5, add = 0;
            for (int q = 0; q < w8; q++) add += wtot[q];
            hist2[tid] = inc + add;
        }
        __syncthreads();
        if (tid < 256) {
            int sfx = hist2[tid];
            int above = (tid == 0) ? 0 : hist2[tid - 1];
            if (sfx >= remaining && above < remaining) {
                s_sel[0] = 255 - tid;
                s_sel[1] = above;
            }
        }
        __syncthreads();
        prefixK |= ((unsigned int)s_sel[0]) << shift;
        pmask   |= 255u << shift;
        remaining -= s_sel[1];
        __syncthreads();
    }
    unsigned int T = prefixK;
    int R = remaining;

    // ---- stable compaction ----
    int strict = (key > T) ? 1 : 0;
    int tie    = (key == T) ? 1 : 0;
    int pk = strict | (tie << 16);
    int incs = pk;
    #pragma unroll
    for (int o = 1; o < 32; o <<= 1) {
        int t = __shfl_up_sync(0xffffffffu, incs, o);
        if (lane >= o) incs += t;
    }
    int* wsum = hist;
    if (lane == 31) wsum[wid] = incs;
    __syncthreads();
    if (wid == 0) {
        int ws = wsum[lane], wi = ws;
        #pragma unroll
        for (int o = 1; o < 32; o <<= 1) {
            int t = __shfl_up_sync(0xffffffffu, wi, o);
            if (lane >= o) wi += t;
        }
        wsum[lane] = wi - ws;
    }
    __syncthreads();
    int before = wsum[wid] + incs - pk;
    int sk_before  = before & 0xFFFF;
    int tie_before = before >> 16;
    int acc_f = strict | (tie & (tie_before < R ? 1 : 0));
    int newid = sk_before + (tie_before < R ? tie_before : R);
    s_map[tid] = acc_f ? newid : -1;
    if (acc_f) s_perm[newid] = tid;
    __syncthreads();

    // publish map/perm for the wide compact kernel
    if (b < 3) {
        if (tid < ncur) g_mapG[g * ncur + tid] = s_map[tid];
        if (tid < ksel) g_permG[g * ksel + tid] = s_perm[tid];
    }

    // ---- gather + tanh gate + readout ----
    float4 rsum = make_float4(0.f, 0.f, 0.f, 0.f);
    float4 rmax = make_float4(-FLT_MAX, -FLT_MAX, -FLT_MAX, -FLT_MAX);
    for (int nw = wid; nw < ksel; nw += 32) {
        int old = s_perm[nw];
        float t = tanhf(s_score[old]);
        float4 h = *(const float4*)(g_bufB + (size_t)(g * ncur + old) * H_ + c);
        h.x *= t; h.y *= t; h.z *= t; h.w *= t;
        if (b < 3) *(float4*)(g_bufA + (size_t)(g * ksel + nw) * H_ + c) = h;
        rsum.x += h.x; rsum.y += h.y; rsum.z += h.z; rsum.w += h.w;
        rmax.x = fmaxf(rmax.x, h.x); rmax.y = fmaxf(rmax.y, h.y);
        rmax.z = fmaxf(rmax.z, h.z); rmax.w = fmaxf(rmax.w, h.w);
    }
    __syncthreads();
    *(float4*)&s_red[wid * 128 + c]        = rsum;
    *(float4*)&s_red[4096 + wid * 128 + c] = rmax;
    __syncthreads();
    if (tid < 128) {
        float s = 0.f, m = -FLT_MAX;
        #pragma unroll
        for (int w = 0; w < 32; w++) {
            s += s_red[w * 128 + tid];
            m = fmaxf(m, s_red[4096 + w * 128 + tid]);
        }
        g_flat[g * 1024 + b * 256 + tid]       = s;
        g_flat[g * 1024 + b * 256 + 128 + tid] = m;
    }

    if (b == 3) {
        __syncthreads();
        float* a = (float*)s_map;
        a[tid] = g_flat[g * 1024 + tid];
        __syncthreads();
        float* hd = (float*)s_cnt;
        if (tid < 512) {
            float a0 = 0.f, a1 = 0.f, a2 = 0.f, a3 = 0.f;
            #pragma unroll 4
            for (int kk = 0; kk < 1024; kk += 4) {
                a0 += a[kk + 0] * Wd1[(kk + 0) * 512 + tid];
                a1 += a[kk + 1] * Wd1[(kk + 1) * 512 + tid];
                a2 += a[kk + 2] * Wd1[(kk + 2) * 512 + tid];
                a3 += a[kk + 3] * Wd1[(kk + 3) * 512 + tid];
            }
            hd[tid] = fmaxf(a0 + a1 + a2 + a3 + bd1[tid], 0.f);
        }
        __syncthreads();
        if (tid < 320) {
            int cc = tid >> 5, l = tid & 31;
            float acc = 0.f;
            for (int kk = l; kk < 512; kk += 32) acc += hd[kk] * Wd2[kk * 10 + cc];
            #pragma unroll
            for (int o = 16; o > 0; o >>= 1) acc += __shfl_down_sync(0xffffffffu, acc, o);
            if (l == 0) out[g * 10 + cc] = acc + bd2[cc];
        }
    }
}

// ---------------- launcher ----------------
extern "C" void kernel_launch(void* const* d_in, const int* in_sizes, int n_in,
                              void* d_out, int out_size) {
    const float* x  = (const float*)d_in[0];
    const int*   ei = (const int*)d_in[1];
    const float *Wl[4], *Wr[4], *bb[4], *gw[4], *be[4], *pp[4];
    int idx = 3;
    for (int b = 0; b < 4; b++) {
        Wl[b] = (const float*)d_in[idx++];
        Wr[b] = (const float*)d_in[idx++];
        bb[b] = (const float*)d_in[idx++];
        gw[b] = (const float*)d_in[idx++];
        be[b] = (const float*)d_in[idx++];
        pp[b] = (const float*)d_in[idx++];
    }
    const float* Wd1 = (const float*)d_in[27];
    const float* bd1 = (const float*)d_in[28];
    const float* Wd2 = (const float*)d_in[29];
    const float* bd2 = (const float*)d_in[30];
    float* out = (float*)d_out;

    cudaFuncSetAttribute(gemm_kernel, cudaFuncAttributeMaxDynamicSharedMemorySize,
                         SMEM_GEMM_BYTES);
    cudaFuncSetAttribute(mega_kernel, cudaFuncAttributeMaxDynamicSharedMemorySize,
                         MEGA_SMEM);

    csr0_kernel<<<G_, 1024>>>(ei);

    for (int b = 0; b < 4; b++) {
        int ncur = NCUR_H[b];
        int k    = KSEL_H[b];
        int nt   = G_ * ncur;
        int first = (b == 0) ? 1 : 0;
        int sel   = b & 1;       // read buffer parity

        gemm_kernel<<<(nt + 63) / 64, 256, SMEM_GEMM_BYTES>>>(
            x, first, b, sel, Wl[b], Wr[b], bb[b], nt);
        bnscore_kernel<<<(nt + 7) / 8, 256>>>(gw[b], be[b], pp[b], nt, 1.0f / (float)nt, b);
        mega_kernel<<<G_, 1024, MEGA_SMEM>>>(
            b, ncur, k, Wd1, bd1, Wd2, bd2, out);
        if (b < 3)
            compact_kernel<<<(G_ * k * 32 + 255) / 256, 256>>>(ncur, k, sel);
    }
}

// round 13
// speedup vs baseline: 1.2113x; 1.0751x over previous
#include <cuda_runtime.h>
#include <math.h>
#include <float.h>

// ---------------- problem constants ----------------
#define G_      32
#define EPG     16384                 // edges per graph
#define EDGES   (G_ * EPG)
#define H_      128
#define NT_MAX  32768

static const int NCUR_H[4] = {1024, 820, 656, 525};
static const int KSEL_H[4] = {820, 656, 525, 420};

// gemm smem: meanS 64x132 + W 2x16x128 + H 2x16x64  (floats)
#define SMEM_GEMM_BYTES ((64 * 132 + 2 * 16 * 128 + 2 * 16 * 64) * 4)
// mega smem (select only now, keep generous)
#define MEGA_SMEM (3 * 4096 + 4096)

// ---------------- device scratch (double-buffered pooled CSR) ----------------
__device__ __align__(16) float g_bufA[NT_MAX * H_];  // pooled h (input of next block)
__device__ __align__(16) float g_bufB[NT_MAX * H_];  // conv out -> BN'd h
__device__ int   g_cnt0[NT_MAX],  g_cnt1[NT_MAX];    // surviving in-degree per node
__device__ int   g_off0[NT_MAX],  g_off1[NT_MAX];    // absolute csr base per node
__device__ int   g_csrA[EDGES],   g_csrB[EDGES];     // neighbor global ids grouped by dst
__device__ int   g_mapG[NT_MAX];   // current global id -> new local id (-1)
__device__ int   g_permG[NT_MAX];  // new global id (g*ksel+nw) -> old current local id
__device__ float g_score[NT_MAX];
__device__ __align__(16) float g_colsum[4 * H_];
__device__ __align__(16) float g_colsq [4 * H_];
__device__ float g_flat[G_ * 1024];                  // sums at [g*1024 + b*256 + j]
__device__ unsigned int g_fmax[G_ * 4 * 128];        // orderable-uint maxes

// ---------------- csr0: per-graph count+scan+fill + zero accumulators ----------------
__global__ __launch_bounds__(1024)
void csr0_kernel(const int* __restrict__ ei) {
    __shared__ int cnt[1024], off[1024], cur[1024];
    __shared__ int wsum[32];
    int g = blockIdx.x, tid = threadIdx.x;
    int lane = tid & 31, wid = tid >> 5;
    cnt[tid] = 0;
    __syncthreads();
    const int* srcp = ei + g * EPG;
    const int* dstp = ei + EDGES + g * EPG;
    for (int e = tid; e < EPG; e += 1024)
        atomicAdd(&cnt[dstp[e] - (g << 10)], 1);
    __syncthreads();
    int v = cnt[tid];
    int inc = v;
    #pragma unroll
    for (int o = 1; o < 32; o <<= 1) {
        int t = __shfl_up_sync(0xffffffffu, inc, o);
        if (lane >= o) inc += t;
    }
    if (lane == 31) wsum[wid] = inc;
    __syncthreads();
    if (wid == 0) {
        int ws = wsum[lane], wi = ws;
        #pragma unroll
        for (int o = 1; o < 32; o <<= 1) {
            int t = __shfl_up_sync(0xffffffffu, wi, o);
            if (lane >= o) wi += t;
        }
        wsum[lane] = wi - ws;
    }
    __syncthreads();
    int ex = wsum[wid] + inc - v;
    off[tid] = ex;
    g_off0[g * 1024 + tid] = g * EPG + ex;
    g_cnt0[g * 1024 + tid] = v;
    cur[tid] = 0;
    __syncthreads();
    for (int e = tid; e < EPG; e += 1024) {
        int s = srcp[e];                      // global node id
        int d = dstp[e] - (g << 10);
        int pos = atomicAdd(&cur[d], 1);
        g_csrA[g * EPG + off[d] + pos] = s;
    }
    // zero per-run accumulators (re-zeroed every replay)
    int i = g * 1024 + tid;
    g_flat[i] = 0.f;
    if (i < G_ * 4 * 128) g_fmax[i] = 0u;
    if (g == 0 && tid < 4 * H_) { g_colsum[tid] = 0.f; g_colsq[tid] = 0.f; }
}

// ---------------- wide CSR compaction: old pooled CSR -> new pooled CSR ----------------
__global__ __launch_bounds__(256)
void compact_kernel(int ncur, int ksel, int sel) {
    const int* ocnt = sel ? g_cnt1 : g_cnt0;
    const int* ooff = sel ? g_off1 : g_off0;
    const int* ocsr = sel ? g_csrB : g_csrA;
    int* ncnt = sel ? g_cnt0 : g_cnt1;
    int* noff = sel ? g_off0 : g_off1;
    int* ncsr = sel ? g_csrA : g_csrB;

    int n = (blockIdx.x * blockDim.x + threadIdx.x) >> 5;
    int lane = threadIdx.x & 31;
    if (n >= G_ * ksel) return;
    int g = n / ksel;
    int og = g * ncur + g_permG[n];
    int deg  = ocnt[og];
    int base = ooff[og];
    int gk = g * ksel;
    int cum = 0;
    for (int j0 = 0; j0 < deg; j0 += 32) {
        int j = j0 + lane;
        int m = -1;
        if (j < deg) m = g_mapG[ocsr[base + j]];
        unsigned int mk = __ballot_sync(0xffffffffu, m >= 0);
        if (m >= 0) {
            int pos = __popc(mk & ((1u << lane) - 1u));
            ncsr[base + cum + pos] = gk + m;
        }
        cum += __popc(mk);
    }
    if (lane == 0) { ncnt[n] = cum; noff[n] = base; }
}

// ---------------- fused gather-mean + GEMM + BN-stats (64-row tile) ----------------
__global__ __launch_bounds__(256, 3)
void gemm_kernel(const float* __restrict__ x, int first, int slot, int sel,
                 const float* __restrict__ Wl, const float* __restrict__ Wr,
                 const float* __restrict__ bb, int nt) {
    extern __shared__ float smem[];
    float* meanS = smem;                        // [64][132]
    float* WshB  = smem + 64 * 132;             // [2][16][128]
    float* HshB  = WshB + 2 * 16 * 128;         // [2][16][64]
    #define WSH(bf,k,c) WshB[(bf) * 2048 + (k) * 128 + (c)]
    #define HSH(bf,k,m) HshB[(bf) * 1024 + (k) * 64 + (m)]

    const int* cnti = sel ? g_cnt1 : g_cnt0;
    const int* offi = sel ? g_off1 : g_off0;
    const int* csri = sel ? g_csrB : g_csrA;

    const float* hin = first ? x : g_bufA;
    int row0 = blockIdx.x * 64;
    int tid = threadIdx.x;
    int w = tid >> 5, lane = tid & 31;
    int tx = tid & 15, ty = tid >> 4;
    int rm = ty * 4, cn = tx * 4;

    float4 pw[2];
    #pragma unroll
    for (int i = 0; i < 2; i++) {
        int idx = tid * 2 + i;
        int kk = idx >> 5, c = (idx & 31) * 4;
        pw[i] = *(const float4*)(Wl + (size_t)kk * H_ + c);
    }

    // ---- phase 1: gather means ----
    for (int i = 0; i < 8; i++) {
        int rl = w * 8 + i;
        int row = row0 + rl;
        float4 acc = make_float4(0.f, 0.f, 0.f, 0.f);
        if (row < nt) {
            int deg  = cnti[row];
            int base = offi[row];
            int j = 0;
            for (; j + 8 <= deg; j += 8) {
                int s0 = csri[base + j + 0];
                int s1 = csri[base + j + 1];
                int s2 = csri[base + j + 2];
                int s3 = csri[base + j + 3];
                int s4 = csri[base + j + 4];
                int s5 = csri[base + j + 5];
                int s6 = csri[base + j + 6];
                int s7 = csri[base + j + 7];
                float4 v0 = *((const float4*)(hin + (size_t)s0 * H_) + lane);
                float4 v1 = *((const float4*)(hin + (size_t)s1 * H_) + lane);
                float4 v2 = *((const float4*)(hin + (size_t)s2 * H_) + lane);
                float4 v3 = *((const float4*)(hin + (size_t)s3 * H_) + lane);
                float4 v4 = *((const float4*)(hin + (size_t)s4 * H_) + lane);
                float4 v5 = *((const float4*)(hin + (size_t)s5 * H_) + lane);
                float4 v6 = *((const float4*)(hin + (size_t)s6 * H_) + lane);
                float4 v7 = *((const float4*)(hin + (size_t)s7 * H_) + lane);
                acc.x += ((v0.x + v1.x) + (v2.x + v3.x)) + ((v4.x + v5.x) + (v6.x + v7.x));
                acc.y += ((v0.y + v1.y) + (v2.y + v3.y)) + ((v4.y + v5.y) + (v6.y + v7.y));
                acc.z += ((v0.z + v1.z) + (v2.z + v3.z)) + ((v4.z + v5.z) + (v6.z + v7.z));
                acc.w += ((v0.w + v1.w) + (v2.w + v3.w)) + ((v4.w + v5.w) + (v6.w + v7.w));
            }
            for (; j < deg; j++) {
                int s0 = csri[base + j];
                float4 a = *((const float4*)(hin + (size_t)s0 * H_) + lane);
                acc.x += a.x; acc.y += a.y; acc.z += a.z; acc.w += a.w;
            }
            float inv = 1.0f / fmaxf((float)deg, 1.0f);
            acc.x *= inv; acc.y *= inv; acc.z *= inv; acc.w *= inv;
        }
        *(float4*)&meanS[rl * 132 + lane * 4] = acc;
    }
    #pragma unroll
    for (int i = 0; i < 2; i++) {
        int idx = tid * 2 + i;
        int kk = idx >> 5, c = (idx & 31) * 4;
        *(float4*)&WSH(0, kk, c) = pw[i];
    }
    __syncthreads();

    float acc[4][8];
    #pragma unroll
    for (int i = 0; i < 4; i++)
        #pragma unroll
        for (int j = 0; j < 8; j++) acc[i][j] = 0.f;

    int cur = 0;
    float4 ph;

    for (int kbi = 0; kbi < 8; kbi++) {
        int kwb = (kbi + 1) * 16;
        #pragma unroll
        for (int i = 0; i < 2; i++) {
            int idx = tid * 2 + i;
            int kk = idx >> 5, c = (idx & 31) * 4;
            int kw = kwb + kk;
            const float* ws = (kw < 128) ? (Wl + (size_t)kw * H_ + c)
                                         : (Wr + (size_t)(kw - 128) * H_ + c);
            pw[i] = *(const float4*)ws;
        }
        if (kbi == 7) {
            int r = tid >> 2, kc = (tid & 3) * 4;
            int row = row0 + r;
            ph = (row < nt) ? *(const float4*)(hin + (size_t)row * H_ + kc)
                            : make_float4(0.f, 0.f, 0.f, 0.f);
        }
        int kb = kbi * 16;
        #pragma unroll
        for (int kk = 0; kk < 16; kk++) {
            int kcol = kb + kk;
            float a[4];
            #pragma unroll
            for (int i = 0; i < 4; i++) a[i] = meanS[(rm + i) * 132 + kcol];
            float4 b0 = *(const float4*)&WSH(cur, kk, cn);
            float4 b1 = *(const float4*)&WSH(cur, kk, cn + 64);
            float bv[8] = {b0.x, b0.y, b0.z, b0.w, b1.x, b1.y, b1.z, b1.w};
            #pragma unroll
            for (int i = 0; i < 4; i++)
                #pragma unroll
                for (int j = 0; j < 8; j++)
                    acc[i][j] += a[i] * bv[j];
        }
        #pragma unroll
        for (int i = 0; i < 2; i++) {
            int idx = tid * 2 + i;
            int kk = idx >> 5, c = (idx & 31) * 4;
            *(float4*)&WSH(cur ^ 1, kk, c) = pw[i];
        }
        if (kbi == 7) {
            int r = tid >> 2, kc = (tid & 3) * 4;
            HSH(cur ^ 1, kc + 0, r) = ph.x;
            HSH(cur ^ 1, kc + 1, r) = ph.y;
            HSH(cur ^ 1, kc + 2, r) = ph.z;
            HSH(cur ^ 1, kc + 3, r) = ph.w;
        }
        __syncthreads();
        cur ^= 1;
    }

    for (int kbi = 8; kbi < 16; kbi++) {
        if (kbi < 15) {
            int kwb = (kbi + 1) * 16;
            int hb  = (kbi + 1 - 8) * 16;
            #pragma unroll
            for (int i = 0; i < 2; i++) {
                int idx = tid * 2 + i;
                int kk = idx >> 5, c = (idx & 31) * 4;
                pw[i] = *(const float4*)(Wr + (size_t)(kwb + kk - 128) * H_ + c);
            }
            int r = tid >> 2, kc = (tid & 3) * 4;
            int row = row0 + r;
            ph = (row < nt) ? *(const float4*)(hin + (size_t)row * H_ + hb + kc)
                            : make_float4(0.f, 0.f, 0.f, 0.f);
        }
        #pragma unroll
        for (int kk = 0; kk < 16; kk++) {
            float4 a0 = *(const float4*)&HSH(cur, kk, rm);
            float4 b0 = *(const float4*)&WSH(cur, kk, cn);
            float4 b1 = *(const float4*)&WSH(cur, kk, cn + 64);
            float a[4] = {a0.x, a0.y, a0.z, a0.w};
            float bv[8] = {b0.x, b0.y, b0.z, b0.w, b1.x, b1.y, b1.z, b1.w};
            #pragma unroll
            for (int i = 0; i < 4; i++)
                #pragma unroll
                for (int j = 0; j < 8; j++)
                    acc[i][j] += a[i] * bv[j];
        }
        if (kbi < 15) {
            #pragma unroll
            for (int i = 0; i < 2; i++) {
                int idx = tid * 2 + i;
                int kk = idx >> 5, c = (idx & 31) * 4;
                *(float4*)&WSH(cur ^ 1, kk, c) = pw[i];
            }
            int r = tid >> 2, kc = (tid & 3) * 4;
            HSH(cur ^ 1, kc + 0, r) = ph.x;
            HSH(cur ^ 1, kc + 1, r) = ph.y;
            HSH(cur ^ 1, kc + 2, r) = ph.z;
            HSH(cur ^ 1, kc + 3, r) = ph.w;
        }
        __syncthreads();
        cur ^= 1;
    }

    // ---- epilogue ----
    float4 bia0 = *(const float4*)&bb[cn];
    float4 bia1 = *(const float4*)&bb[cn + 64];
    float bias[8] = {bia0.x, bia0.y, bia0.z, bia0.w, bia1.x, bia1.y, bia1.z, bia1.w};
    float psum[8], psq[8];
    #pragma unroll
    for (int j = 0; j < 8; j++) { psum[j] = 0.f; psq[j] = 0.f; }
    #pragma unroll
    for (int i = 0; i < 4; i++) {
        int row = row0 + rm + i;
        if (row < nt) {
            float v[8];
            #pragma unroll
            for (int j = 0; j < 8; j++) {
                v[j] = acc[i][j] + bias[j];
                psum[j] += v[j];
                psq[j]  += v[j] * v[j];
            }
            *(float4*)(g_bufB + (size_t)row * H_ + cn)      = make_float4(v[0], v[1], v[2], v[3]);
            *(float4*)(g_bufB + (size_t)row * H_ + cn + 64) = make_float4(v[4], v[5], v[6], v[7]);
        }
    }
    __syncthreads();
    float* sumS = meanS;          // [16][128]
    float* sqS  = meanS + 2048;   // [16][128]
    #pragma unroll
    for (int j = 0; j < 4; j++) {
        sumS[ty * 128 + cn + j]      = psum[j];
        sumS[ty * 128 + cn + 64 + j] = psum[4 + j];
        sqS [ty * 128 + cn + j]      = psq[j];
        sqS [ty * 128 + cn + 64 + j] = psq[4 + j];
    }
    __syncthreads();
    if (tid < 128) {
        float s = 0.f, q = 0.f;
        #pragma unroll
        for (int t = 0; t < 16; t++) {
            s += sumS[t * 128 + tid];
            q += sqS [t * 128 + tid];
        }
        atomicAdd(&g_colsum[slot * H_ + tid], s);
        atomicAdd(&g_colsq [slot * H_ + tid], q);
    }
    #undef WSH
    #undef HSH
}

// ---------------- wide BN + ReLU + score ----------------
__global__ __launch_bounds__(256)
void bnscore_kernel(const float* __restrict__ gw, const float* __restrict__ be,
                    const float* __restrict__ p, int nt, float invnt, int slot) {
    int row = blockIdx.x * 8 + (threadIdx.x >> 5);
    int lane = threadIdx.x & 31;
    if (row >= nt) return;
    int c = lane * 4;
    float4 h  = *(const float4*)(g_bufB + (size_t)row * H_ + c);
    float4 cs = *(const float4*)&g_colsum[slot * H_ + c];
    float4 cq = *(const float4*)&g_colsq [slot * H_ + c];
    float4 gv = *(const float4*)&gw[c];
    float4 bv = *(const float4*)&be[c];
    float4 pv = *(const float4*)&p[c];
    float hh[4]  = {h.x, h.y, h.z, h.w};
    float css[4] = {cs.x, cs.y, cs.z, cs.w};
    float cqq[4] = {cq.x, cq.y, cq.z, cq.w};
    float gg[4]  = {gv.x, gv.y, gv.z, gv.w};
    float bbv[4] = {bv.x, bv.y, bv.z, bv.w};
    float pp[4]  = {pv.x, pv.y, pv.z, pv.w};
    float out[4];
    float dot = 0.f, pn = 0.f;
    #pragma unroll
    for (int j = 0; j < 4; j++) {
        float mu = css[j] * invnt;
        float var = cqq[j] * invnt - mu * mu;
        float r = rsqrtf(var + 1e-5f);
        float v = (hh[j] - mu) * r * gg[j] + bbv[j];
        v = fmaxf(v, 0.f);
        out[j] = v;
        dot += v * pp[j];
        pn  += pp[j] * pp[j];
    }
    *(float4*)(g_bufB + (size_t)row * H_ + c) = make_float4(out[0], out[1], out[2], out[3]);
    #pragma unroll
    for (int o = 16; o > 0; o >>= 1) {
        dot += __shfl_down_sync(0xffffffffu, dot, o);
        pn  += __shfl_down_sync(0xffffffffu, pn, o);
    }
    if (lane == 0) g_score[row] = dot * rsqrtf(pn);
}

// ---------------- mega: radix-select -> publish map/perm ----------------
__global__ __launch_bounds__(1024)
void mega_kernel(int b, int ncur, int ksel) {
    extern __shared__ char smx[];
    int*   s_perm  = (int*)(smx);              // [1024]
    int*   s_map   = (int*)(smx + 4096);       // [1024]
    int*   s_red   = (int*)(smx + 8192);       // select scratch (>= 546 ints)

    int g = blockIdx.x, tid = threadIdx.x;
    int lane = tid & 31, wid = tid >> 5;

    float myscore = (tid < ncur) ? g_score[g * ncur + tid] : -FLT_MAX;
    unsigned int key = 0u;
    if (tid < ncur) {
        unsigned int u = __float_as_uint(myscore);
        key = (u & 0x80000000u) ? ~u : (u | 0x80000000u);
    }

    int* hist  = s_red;
    int* hist2 = hist + 256;
    int* wtot  = hist + 512;
    int* s_sel = hist + 544;
    unsigned int prefixK = 0u, pmask = 0u;
    int remaining = ksel;
    #pragma unroll
    for (int pass = 0; pass < 4; pass++) {
        int shift = 24 - pass * 8;
        if (tid < 256) hist[tid] = 0;
        __syncthreads();
        if ((key & pmask) == prefixK)
            atomicAdd(&hist[(key >> shift) & 255u], 1);
        __syncthreads();
        int inc = 0;
        if (tid < 256) {
            inc = hist[255 - tid];
            #pragma unroll
            for (int o = 1; o < 32; o <<= 1) {
                int t = __shfl_up_sync(0xffffffffu, inc, o);
                if (lane >= o) inc += t;
            }
            if (lane == 31) wtot[tid >> 5] = inc;
        }
        __syncthreads();
        if (tid < 256) {
            int w8 = tid >> 5, add = 0;
            for (int q = 0; q < w8; q++) add += wtot[q];
            hist2[tid] = inc + add;
        }
        __syncthreads();
        if (tid < 256) {
            int sfx = hist2[tid];
            int above = (tid == 0) ? 0 : hist2[tid - 1];
            if (sfx >= remaining && above < remaining) {
                s_sel[0] = 255 - tid;
                s_sel[1] = above;
            }
        }
        __syncthreads();
        prefixK |= ((unsigned int)s_sel[0]) << shift;
        pmask   |= 255u << shift;
        remaining -= s_sel[1];
        __syncthreads();
    }
    unsigned int T = prefixK;
    int R = remaining;

    int strict = (key > T) ? 1 : 0;
    int tie    = (key == T) ? 1 : 0;
    int pk = strict | (tie << 16);
    int incs = pk;
    #pragma unroll
    for (int o = 1; o < 32; o <<= 1) {
        int t = __shfl_up_sync(0xffffffffu, incs, o);
        if (lane >= o) incs += t;
    }
    int* wsum = hist;
    if (lane == 31) wsum[wid] = incs;
    __syncthreads();
    if (wid == 0) {
        int ws = wsum[lane], wi = ws;
        #pragma unroll
        for (int o = 1; o < 32; o <<= 1) {
            int t = __shfl_up_sync(0xffffffffu, wi, o);
            if (lane >= o) wi += t;
        }
        wsum[lane] = wi - ws;
    }
    __syncthreads();
    int before = wsum[wid] + incs - pk;
    int sk_before  = before & 0xFFFF;
    int tie_before = before >> 16;
    int acc_f = strict | (tie & (tie_before < R ? 1 : 0));
    int newid = sk_before + (tie_before < R ? tie_before : R);
    s_map[tid] = acc_f ? newid : -1;
    if (acc_f) s_perm[newid] = tid;
    __syncthreads();

    if (tid < ncur && b < 3) g_mapG[g * ncur + tid] = s_map[tid];
    if (tid < ksel) g_permG[g * ksel + tid] = s_perm[tid];
}

// ---------------- wide gather + tanh gate + readout partials ----------------
__global__ __launch_bounds__(256)
void gatherread_kernel(int b, int ncur, int ksel) {
    __shared__ float ssum[8][128];
    __shared__ unsigned int smax[8][128];
    int g = blockIdx.x;
    int row0 = blockIdx.y * 32;
    int tid = threadIdx.x, wid = tid >> 5, lane = tid & 31;
    int c = lane * 4;
    float4 rsum = make_float4(0.f, 0.f, 0.f, 0.f);
    float4 rmax = make_float4(-FLT_MAX, -FLT_MAX, -FLT_MAX, -FLT_MAX);
    #pragma unroll
    for (int r = 0; r < 4; r++) {
        int nw = row0 + wid * 4 + r;
        if (nw < ksel) {
            int old = g_permG[g * ksel + nw];
            float t = tanhf(g_score[g * ncur + old]);
            float4 h = *((const float4*)(g_bufB + (size_t)(g * ncur + old) * H_) + lane);
            h.x *= t; h.y *= t; h.z *= t; h.w *= t;
            if (b < 3) *((float4*)(g_bufA + (size_t)(g * ksel + nw) * H_) + lane) = h;
            rsum.x += h.x; rsum.y += h.y; rsum.z += h.z; rsum.w += h.w;
            rmax.x = fmaxf(rmax.x, h.x); rmax.y = fmaxf(rmax.y, h.y);
            rmax.z = fmaxf(rmax.z, h.z); rmax.w = fmaxf(rmax.w, h.w);
        }
    }
    *(float4*)&ssum[wid][c] = rsum;
    {
        unsigned int ux = __float_as_uint(rmax.x);
        unsigned int uy = __float_as_uint(rmax.y);
        unsigned int uz = __float_as_uint(rmax.z);
        unsigned int uw = __float_as_uint(rmax.w);
        smax[wid][c + 0] = (ux & 0x80000000u) ? ~ux : (ux | 0x80000000u);
        smax[wid][c + 1] = (uy & 0x80000000u) ? ~uy : (uy | 0x80000000u);
        smax[wid][c + 2] = (uz & 0x80000000u) ? ~uz : (uz | 0x80000000u);
        smax[wid][c + 3] = (uw & 0x80000000u) ? ~uw : (uw | 0x80000000u);
    }
    __syncthreads();
    if (tid < 128) {
        float s = 0.f;
        unsigned int m = 0u;
        #pragma unroll
        for (int w = 0; w < 8; w++) {
            s += ssum[w][tid];
            m = max(m, smax[w][tid]);
        }
        atomicAdd(&g_flat[g * 1024 + b * 256 + tid], s);
        atomicMax(&g_fmax[(g * 4 + b) * 128 + tid], m);
    }
}

// ---------------- MLP head (runs once, after block 3) ----------------
__global__ __launch_bounds__(512)
void head_kernel(const float* __restrict__ Wd1, const float* __restrict__ bd1,
                 const float* __restrict__ Wd2, const float* __restrict__ bd2,
                 float* __restrict__ out) {
    __shared__ float a[1024];
    __shared__ float hd[512];
    int g = blockIdx.x, tid = threadIdx.x;
    for (int j = tid; j < 1024; j += 512) {
        int bb = j >> 8, r = j & 255;
        float v;
        if (r < 128) {
            v = g_flat[g * 1024 + bb * 256 + r];
        } else {
            unsigned int u = g_fmax[(g * 4 + bb) * 128 + (r - 128)];
            v = (u & 0x80000000u) ? __uint_as_float(u ^ 0x80000000u)
                                  : __uint_as_float(~u);
        }
        a[j] = v;
    }
    __syncthreads();
    {
        float a0 = 0.f, a1 = 0.f, a2 = 0.f, a3 = 0.f;
        #pragma unroll 4
        for (int kk = 0; kk < 1024; kk += 4) {
            a0 += a[kk + 0] * Wd1[(kk + 0) * 512 + tid];
            a1 += a[kk + 1] * Wd1[(kk + 1) * 512 + tid];
            a2 += a[kk + 2] * Wd1[(kk + 2) * 512 + tid];
            a3 += a[kk + 3] * Wd1[(kk + 3) * 512 + tid];
        }
        hd[tid] = fmaxf(a0 + a1 + a2 + a3 + bd1[tid], 0.f);
    }
    __syncthreads();
    if (tid < 320) {
        int cc = tid >> 5, l = tid & 31;
        float acc = 0.f;
        for (int kk = l; kk < 512; kk += 32) acc += hd[kk] * Wd2[kk * 10 + cc];
        #pragma unroll
        for (int o = 16; o > 0; o >>= 1) acc += __shfl_down_sync(0xffffffffu, acc, o);
        if (l == 0) out[g * 10 + cc] = acc + bd2[cc];
    }
}

// ---------------- launcher ----------------
extern "C" void kernel_launch(void* const* d_in, const int* in_sizes, int n_in,
                              void* d_out, int out_size) {
    const float* x  = (const float*)d_in[0];
    const int*   ei = (const int*)d_in[1];
    const float *Wl[4], *Wr[4], *bb[4], *gw[4], *be[4], *pp[4];
    int idx = 3;
    for (int b = 0; b < 4; b++) {
        Wl[b] = (const float*)d_in[idx++];
        Wr[b] = (const float*)d_in[idx++];
        bb[b] = (const float*)d_in[idx++];
        gw[b] = (const float*)d_in[idx++];
        be[b] = (const float*)d_in[idx++];
        pp[b] = (const float*)d_in[idx++];
    }
    const float* Wd1 = (const float*)d_in[27];
    const float* bd1 = (const float*)d_in[28];
    const float* Wd2 = (const float*)d_in[29];
    const float* bd2 = (const float*)d_in[30];
    float* out = (float*)d_out;

    cudaFuncSetAttribute(gemm_kernel, cudaFuncAttributeMaxDynamicSharedMemorySize,
                         SMEM_GEMM_BYTES);
    cudaFuncSetAttribute(mega_kernel, cudaFuncAttributeMaxDynamicSharedMemorySize,
                         MEGA_SMEM);

    csr0_kernel<<<G_, 1024>>>(ei);

    for (int b = 0; b < 4; b++) {
        int ncur = NCUR_H[b];
        int k    = KSEL_H[b];
        int nt   = G_ * ncur;
        int first = (b == 0) ? 1 : 0;
        int sel   = b & 1;       // read buffer parity

        gemm_kernel<<<(nt + 63) / 64, 256, SMEM_GEMM_BYTES>>>(
            x, first, b, sel, Wl[b], Wr[b], bb[b], nt);
        bnscore_kernel<<<(nt + 7) / 8, 256>>>(gw[b], be[b], pp[b], nt, 1.0f / (float)nt, b);
        mega_kernel<<<G_, 1024, MEGA_SMEM>>>(b, ncur, k);
        gatherread_kernel<<<dim3(G_, (k + 31) / 32), 256>>>(b, ncur, k);
        if (b < 3)
            compact_kernel<<<(G_ * k * 32 + 255) / 256, 256>>>(ncur, k, sel);
    }
    head_kernel<<<G_, 512>>>(Wd1, bd1, Wd2, bd2, out);
}